// round 3
// baseline (speedup 1.0000x reference)
#include <cuda_runtime.h>

#define Bsz 200
#define Tsz 250
#define Fsz 14
#define Hsz 256
#define G4  1024          // 4*H
#define Dsz 164
#define Csz 8

#define HST_LD 36         // padded leading dim for transposed h tile (16B aligned, conflict-reduced)
#define ZS_LD  33
#define PM     128        // proj2 rows per CTA
#define AT_LD  132

// ---------------- scratch (static device globals; no allocation) ----------------
__device__ float g_xz1[Tsz * Bsz * G4];   // [t][b][4H] input projection, layer 1
__device__ float g_xz2[Tsz * Bsz * G4];   // [t][b][4H] input projection, layer 2
__device__ float g_seq[Tsz * Bsz * Hsz];  // [t][b][H]  layer-1 hidden sequence
__device__ float g_h1a[Bsz * Hsz];
__device__ float g_h1b[Bsz * Hsz];
__device__ float g_c1 [Bsz * Hsz];
__device__ float g_h2a[Bsz * Hsz];
__device__ float g_h2b[Bsz * Hsz];
__device__ float g_c2 [Bsz * Hsz];

// ---------------- helpers ----------------
__device__ __forceinline__ unsigned long long pack_dup(float u) {
    unsigned int uu = __float_as_uint(u);
    unsigned long long r;
    asm("mov.b64 %0, {%1, %1};" : "=l"(r) : "r"(uu));
    return r;
}
__device__ __forceinline__ void ffma2(unsigned long long& d, unsigned long long a, unsigned long long b) {
    asm("fma.rn.f32x2 %0, %1, %2, %0;" : "+l"(d) : "l"(a), "l"(b));
}
__device__ __forceinline__ void unpack2(unsigned long long v, float& lo, float& hi) {
    unsigned int l, h;
    asm("mov.b64 {%0, %1}, %2;" : "=r"(l), "=r"(h) : "l"(v));
    lo = __uint_as_float(l);
    hi = __uint_as_float(h);
}
__device__ __forceinline__ float sigmoidf_(float x) {
    return 1.0f / (1.0f + __expf(-x));
}

// ---------------- state init ----------------
__global__ void zero_state() {
    int i = blockIdx.x * blockDim.x + threadIdx.x;
    if (i < Bsz * Hsz) {
        g_h1a[i] = 0.f; g_h1b[i] = 0.f; g_c1[i] = 0.f;
        g_h2a[i] = 0.f; g_h2b[i] = 0.f; g_c2[i] = 0.f;
    }
}

// ---------------- K1: xz1[t][b][c] = inputs[b][t][:] @ W1 + b1 ----------------
// one block per (b,t), 256 threads, 4 cols each
__global__ __launch_bounds__(256) void inproj1(const float* __restrict__ x,
                                               const float* __restrict__ W1,
                                               const float* __restrict__ b1) {
    __shared__ float xs[Fsz];
    int m = blockIdx.x;             // m = b*250 + t
    int b = m / Tsz, t = m % Tsz;
    if (threadIdx.x < Fsz) xs[threadIdx.x] = x[m * Fsz + threadIdx.x];
    __syncthreads();
    int c0 = threadIdx.x * 4;
    float4 acc = *reinterpret_cast<const float4*>(b1 + c0);
    #pragma unroll
    for (int f = 0; f < Fsz; ++f) {
        float xv = xs[f];
        float4 w = *reinterpret_cast<const float4*>(W1 + f * G4 + c0);
        acc.x += xv * w.x; acc.y += xv * w.y; acc.z += xv * w.z; acc.w += xv * w.w;
    }
    *reinterpret_cast<float4*>(g_xz1 + (size_t)(t * Bsz + b) * G4 + c0) = acc;
}

// ---------------- K2/K4: one LSTM step ----------------
// grid (16 col-tiles, 7 row-tiles), 256 threads.
// CTA tile: 32 batch rows x 16 h-cols (= 64 gate columns).
// Per thread: 1 gate column (tx in [0,64)) x 8 rows (4 packed f32x2 accumulators).
__global__ __launch_bounds__(256) void lstm_step(int t, int layer,
                                                 const float* __restrict__ U) {
    extern __shared__ float smem[];
    float* hst = smem;                        // [256][HST_LD] transposed h tile
    float* us  = smem + 256 * HST_LD;         // [256][64] U strip (gate-interleaved cols)
    float* zs  = us + 256 * 64;               // [64][ZS_LD] z exchange buffer

    const float* xz = (layer ? g_xz2 : g_xz1) + (size_t)t * Bsz * G4;
    float* ha = layer ? g_h2a : g_h1a;
    float* hb = layer ? g_h2b : g_h1b;
    float* cp = layer ? g_c2  : g_c1;
    const float* hin = (t & 1) ? hb : ha;
    float*       hout = (t & 1) ? ha : hb;
    float* seqp = layer ? (float*)0 : (g_seq + (size_t)t * Bsz * Hsz);

    const int tid   = threadIdx.x;
    const int jbase = blockIdx.x * 16;
    const int rbase = blockIdx.y * 32;

    // stage h tile (transposed) : hst[k][r] = hin[rbase+r][k]
    for (int idx = tid; idx < 32 * 256; idx += 256) {
        int r = idx >> 8, k = idx & 255;
        int row = rbase + r;
        hst[k * HST_LD + r] = (row < Bsz) ? hin[row * Hsz + k] : 0.f;
    }
    // stage U strip : us[k][cc], cc -> gate g=cc>>4, col j=jbase+(cc&15)
    for (int idx = tid; idx < 256 * 64; idx += 256) {
        int k = idx >> 6, cc = idx & 63;
        us[idx] = U[k * G4 + ((cc >> 4) << 8) + jbase + (cc & 15)];
    }
    __syncthreads();

    const int tx = tid & 63;
    const int ty = tid >> 6;
    const int r0 = ty * 8;
    unsigned long long a0 = 0, a1 = 0, a2 = 0, a3 = 0;
    const float* usl = us + tx;
    const float* hl  = hst + r0;
    #pragma unroll 4
    for (int k = 0; k < 256; ++k) {
        unsigned long long ub = pack_dup(usl[k * 64]);
        ulonglong2 hA = *reinterpret_cast<const ulonglong2*>(hl + k * HST_LD);
        ulonglong2 hB = *reinterpret_cast<const ulonglong2*>(hl + k * HST_LD + 4);
        ffma2(a0, hA.x, ub);
        ffma2(a1, hA.y, ub);
        ffma2(a2, hB.x, ub);
        ffma2(a3, hB.y, ub);
    }

    float z[8];
    unpack2(a0, z[0], z[1]);
    unpack2(a1, z[2], z[3]);
    unpack2(a2, z[4], z[5]);
    unpack2(a3, z[6], z[7]);
    const int col = ((tx >> 4) << 8) + jbase + (tx & 15);
    #pragma unroll
    for (int i = 0; i < 8; ++i) {
        int row = rbase + r0 + i;
        float zi = z[i];
        if (row < Bsz) zi += xz[(size_t)row * G4 + col];
        zs[tx * ZS_LD + r0 + i] = zi;
    }
    __syncthreads();

    // gate combine: 16 j-cols x 32 rows = 512 cells, 2 per thread
    for (int cell = tid; cell < 512; cell += 256) {
        int j = cell & 15, r = cell >> 4;
        int row = rbase + r;
        if (row < Bsz) {
            float zi = zs[( 0 + j) * ZS_LD + r];
            float zf = zs[(16 + j) * ZS_LD + r];
            float zg = zs[(32 + j) * ZS_LD + r];
            float zo = zs[(48 + j) * ZS_LD + r];
            float ig = sigmoidf_(zi);
            float fg = sigmoidf_(zf);
            float gv = tanhf(zg);
            float og = sigmoidf_(zo);
            int idx = row * Hsz + jbase + j;
            float cn = fg * cp[idx] + ig * gv;
            cp[idx] = cn;
            float hn = og * tanhf(cn);
            hout[idx] = hn;
            if (seqp) seqp[idx] = hn;
        }
    }
}

// ---------------- K3: xz2 = seq @ W2 + b2  ([50000,256]x[256,1024]) ----------------
// grid (16 col-tiles, ceil(50000/128) row-tiles), 256 threads.
// CTA tile 128x64; per thread: 1 col x 32 rows (16 packed accumulators).
__global__ __launch_bounds__(256) void proj2(const float* __restrict__ W2,
                                             const float* __restrict__ b2) {
    extern __shared__ float smem[];
    float* At = smem;                   // [256][AT_LD] transposed A tile
    float* ws = smem + 256 * AT_LD;     // [256][64]
    const int tid = threadIdx.x;
    const int nbase = blockIdx.x * 64;
    const int mbase = blockIdx.y * PM;
    const int M = Tsz * Bsz;

    for (int idx = tid; idx < PM * 256; idx += 256) {
        int r = idx >> 8, k = idx & 255;
        int m = mbase + r;
        At[k * AT_LD + r] = (m < M) ? g_seq[(size_t)m * Hsz + k] : 0.f;
    }
    for (int idx = tid; idx < 256 * 64; idx += 256) {
        int k = idx >> 6, cc = idx & 63;
        ws[idx] = W2[k * G4 + nbase + cc];
    }
    __syncthreads();

    const int tx = tid & 63;
    const int ty = tid >> 6;
    const int r0 = ty * 32;
    unsigned long long acc[16];
    #pragma unroll
    for (int i = 0; i < 16; ++i) acc[i] = 0ull;
    const float* wl = ws + tx;
    const float* al = At + r0;
    #pragma unroll 2
    for (int k = 0; k < 256; ++k) {
        unsigned long long ub = pack_dup(wl[k * 64]);
        #pragma unroll
        for (int i = 0; i < 8; ++i) {
            ulonglong2 hv = *reinterpret_cast<const ulonglong2*>(al + k * AT_LD + 4 * i);
            ffma2(acc[2 * i],     hv.x, ub);
            ffma2(acc[2 * i + 1], hv.y, ub);
        }
    }
    float bb = b2[nbase + tx];
    #pragma unroll
    for (int p = 0; p < 16; ++p) {
        int rr = r0 + 4 * (p >> 1) + 2 * (p & 1);
        float lo, hi;
        unpack2(acc[p], lo, hi);
        int m0 = mbase + rr;
        if (m0 < M)     g_xz2[(size_t)m0 * G4 + nbase + tx]       = lo + bb;
        if (m0 + 1 < M) g_xz2[(size_t)(m0 + 1) * G4 + nbase + tx] = hi + bb;
    }
}

// ---------------- K5: dense + relu + dense + softmax ----------------
__global__ __launch_bounds__(256) void head(const float* __restrict__ Wd,
                                            const float* __restrict__ bd,
                                            const float* __restrict__ Ws,
                                            const float* __restrict__ bs,
                                            float* __restrict__ out) {
    __shared__ float hrow[Hsz];
    __shared__ float hid[Dsz];
    __shared__ float lbuf[Csz];
    __shared__ float ebuf[Csz];
    int b = blockIdx.x, tid = threadIdx.x;
    hrow[tid] = g_h2a[b * Hsz + tid];   // final h2 lives in buffer 'a' (T even)
    __syncthreads();
    if (tid < Dsz) {
        float s = bd[tid];
        #pragma unroll 8
        for (int k = 0; k < Hsz; ++k) s += hrow[k] * Wd[k * Dsz + tid];
        hid[tid] = fmaxf(s, 0.f);
    }
    __syncthreads();
    if (tid < Csz) {
        float s = bs[tid];
        for (int d = 0; d < Dsz; ++d) s += hid[d] * Ws[d * Csz + tid];
        lbuf[tid] = s;
    }
    __syncthreads();
    if (tid < Csz) {
        float m = lbuf[0];
        #pragma unroll
        for (int j = 1; j < Csz; ++j) m = fmaxf(m, lbuf[j]);
        ebuf[tid] = __expf(lbuf[tid] - m);
    }
    __syncthreads();
    if (tid < Csz) {
        float sum = 0.f;
        #pragma unroll
        for (int j = 0; j < Csz; ++j) sum += ebuf[j];
        out[b * Csz + tid] = ebuf[tid] / sum;
    }
}

// ---------------- launch ----------------
extern "C" void kernel_launch(void* const* d_in, const int* in_sizes, int n_in,
                              void* d_out, int out_size) {
    (void)in_sizes; (void)n_in; (void)out_size;
    const float* inputs = (const float*)d_in[0];
    const float* W1 = (const float*)d_in[1];
    const float* U1 = (const float*)d_in[2];
    const float* b1 = (const float*)d_in[3];
    const float* W2 = (const float*)d_in[4];
    const float* U2 = (const float*)d_in[5];
    const float* b2 = (const float*)d_in[6];
    const float* Wd = (const float*)d_in[7];
    const float* bd = (const float*)d_in[8];
    const float* Ws = (const float*)d_in[9];
    const float* bs = (const float*)d_in[10];
    float* out = (float*)d_out;
    (void)b1;

    const int SM_STEP = (256 * HST_LD + 256 * 64 + 64 * ZS_LD) * 4;   // ~110.8 KB
    const int SM_PROJ = (256 * AT_LD + 256 * 64) * 4;                 // ~200.7 KB
    cudaFuncSetAttribute(lstm_step, cudaFuncAttributeMaxDynamicSharedMemorySize, SM_STEP);
    cudaFuncSetAttribute(proj2,     cudaFuncAttributeMaxDynamicSharedMemorySize, SM_PROJ);

    zero_state<<<(Bsz * Hsz + 255) / 256, 256>>>();
    inproj1<<<Bsz * Tsz, 256>>>(inputs, W1, (const float*)d_in[3]);

    dim3 sg(16, (Bsz + 31) / 32);
    for (int t = 0; t < Tsz; ++t)
        lstm_step<<<sg, 256, SM_STEP>>>(t, 0, U1);

    proj2<<<dim3(16, (Tsz * Bsz + PM - 1) / PM), 256, SM_PROJ>>>(W2, b2);

    for (int t = 0; t < Tsz; ++t)
        lstm_step<<<sg, 256, SM_STEP>>>(t, 1, U2);

    head<<<Bsz, 256>>>(Wd, bd, Ws, bs, out);
}

// round 4
// speedup vs baseline: 1.0084x; 1.0084x over previous
#include <cuda_runtime.h>

#define Bsz 200
#define Tsz 250
#define Fsz 14
#define Hsz 256
#define G4  1024          // 4*H
#define Dsz 164
#define Csz 8

#define HST_LD 36         // padded leading dim for transposed h tile (16B aligned, conflict-reduced)
#define ZS_LD  33
#define PM     128        // proj2 rows per CTA
#define AT_LD  132

// ---------------- scratch (static device globals; no allocation) ----------------
__device__ float g_xz1[Tsz * Bsz * G4];   // [t][b][4H] input projection, layer 1
__device__ float g_xz2[Tsz * Bsz * G4];   // [t][b][4H] input projection, layer 2
__device__ float g_seq[Tsz * Bsz * Hsz];  // [t][b][H]  layer-1 hidden sequence
__device__ float g_h1a[Bsz * Hsz];
__device__ float g_h1b[Bsz * Hsz];
__device__ float g_c1 [Bsz * Hsz];
__device__ float g_h2a[Bsz * Hsz];
__device__ float g_h2b[Bsz * Hsz];
__device__ float g_c2 [Bsz * Hsz];

// ---------------- helpers ----------------
__device__ __forceinline__ unsigned long long pack_dup(float u) {
    unsigned int uu = __float_as_uint(u);
    unsigned long long r;
    asm("mov.b64 %0, {%1, %1};" : "=l"(r) : "r"(uu));
    return r;
}
__device__ __forceinline__ void ffma2(unsigned long long& d, unsigned long long a, unsigned long long b) {
    asm("fma.rn.f32x2 %0, %1, %2, %0;" : "+l"(d) : "l"(a), "l"(b));
}
__device__ __forceinline__ void unpack2(unsigned long long v, float& lo, float& hi) {
    unsigned int l, h;
    asm("mov.b64 {%0, %1}, %2;" : "=r"(l), "=r"(h) : "l"(v));
    lo = __uint_as_float(l);
    hi = __uint_as_float(h);
}
__device__ __forceinline__ float sigmoidf_(float x) {
    return 1.0f / (1.0f + __expf(-x));
}

// ---------------- state init ----------------
__global__ void zero_state() {
    int i = blockIdx.x * blockDim.x + threadIdx.x;
    if (i < Bsz * Hsz) {
        g_h1a[i] = 0.f; g_h1b[i] = 0.f; g_c1[i] = 0.f;
        g_h2a[i] = 0.f; g_h2b[i] = 0.f; g_c2[i] = 0.f;
    }
}

// ---------------- K1: xz1[t][b][c] = inputs[b][t][:] @ W1 + b1 ----------------
// one block per (b,t), 256 threads, 4 cols each
__global__ __launch_bounds__(256) void inproj1(const float* __restrict__ x,
                                               const float* __restrict__ W1,
                                               const float* __restrict__ b1) {
    __shared__ float xs[Fsz];
    int m = blockIdx.x;             // m = b*250 + t
    int b = m / Tsz, t = m % Tsz;
    if (threadIdx.x < Fsz) xs[threadIdx.x] = x[m * Fsz + threadIdx.x];
    __syncthreads();
    int c0 = threadIdx.x * 4;
    float4 acc = *reinterpret_cast<const float4*>(b1 + c0);
    #pragma unroll
    for (int f = 0; f < Fsz; ++f) {
        float xv = xs[f];
        float4 w = *reinterpret_cast<const float4*>(W1 + f * G4 + c0);
        acc.x += xv * w.x; acc.y += xv * w.y; acc.z += xv * w.z; acc.w += xv * w.w;
    }
    *reinterpret_cast<float4*>(g_xz1 + (size_t)(t * Bsz + b) * G4 + c0) = acc;
}

// ---------------- K2/K4: one LSTM step ----------------
// grid (16 col-tiles, 7 row-tiles), 256 threads.
// CTA tile: 32 batch rows x 16 h-cols (= 64 gate columns).
// Per thread: 1 gate column (tx in [0,64)) x 8 rows (4 packed f32x2 accumulators).
__global__ __launch_bounds__(256) void lstm_step(int t, int layer,
                                                 const float* __restrict__ U) {
    extern __shared__ float smem[];
    float* hst = smem;                        // [256][HST_LD] transposed h tile
    float* us  = smem + 256 * HST_LD;         // [256][64] U strip (gate-interleaved cols)
    float* zs  = us + 256 * 64;               // [64][ZS_LD] z exchange buffer

    const float* xz = (layer ? g_xz2 : g_xz1) + (size_t)t * Bsz * G4;
    float* ha = layer ? g_h2a : g_h1a;
    float* hb = layer ? g_h2b : g_h1b;
    float* cp = layer ? g_c2  : g_c1;
    const float* hin = (t & 1) ? hb : ha;
    float*       hout = (t & 1) ? ha : hb;
    float* seqp = layer ? (float*)0 : (g_seq + (size_t)t * Bsz * Hsz);

    const int tid   = threadIdx.x;
    const int jbase = blockIdx.x * 16;
    const int rbase = blockIdx.y * 32;

    // stage h tile (transposed) : hst[k][r] = hin[rbase+r][k]
    for (int idx = tid; idx < 32 * 256; idx += 256) {
        int r = idx >> 8, k = idx & 255;
        int row = rbase + r;
        hst[k * HST_LD + r] = (row < Bsz) ? hin[row * Hsz + k] : 0.f;
    }
    // stage U strip : us[k][cc], cc -> gate g=cc>>4, col j=jbase+(cc&15)
    for (int idx = tid; idx < 256 * 64; idx += 256) {
        int k = idx >> 6, cc = idx & 63;
        us[idx] = U[k * G4 + ((cc >> 4) << 8) + jbase + (cc & 15)];
    }
    __syncthreads();

    const int tx = tid & 63;
    const int ty = tid >> 6;
    const int r0 = ty * 8;
    unsigned long long a0 = 0, a1 = 0, a2 = 0, a3 = 0;
    const float* usl = us + tx;
    const float* hl  = hst + r0;
    #pragma unroll 4
    for (int k = 0; k < 256; ++k) {
        unsigned long long ub = pack_dup(usl[k * 64]);
        ulonglong2 hA = *reinterpret_cast<const ulonglong2*>(hl + k * HST_LD);
        ulonglong2 hB = *reinterpret_cast<const ulonglong2*>(hl + k * HST_LD + 4);
        ffma2(a0, hA.x, ub);
        ffma2(a1, hA.y, ub);
        ffma2(a2, hB.x, ub);
        ffma2(a3, hB.y, ub);
    }

    float z[8];
    unpack2(a0, z[0], z[1]);
    unpack2(a1, z[2], z[3]);
    unpack2(a2, z[4], z[5]);
    unpack2(a3, z[6], z[7]);
    const int col = ((tx >> 4) << 8) + jbase + (tx & 15);
    #pragma unroll
    for (int i = 0; i < 8; ++i) {
        int row = rbase + r0 + i;
        float zi = z[i];
        if (row < Bsz) zi += xz[(size_t)row * G4 + col];
        zs[tx * ZS_LD + r0 + i] = zi;
    }
    __syncthreads();

    // gate combine: 16 j-cols x 32 rows = 512 cells, 2 per thread
    for (int cell = tid; cell < 512; cell += 256) {
        int j = cell & 15, r = cell >> 4;
        int row = rbase + r;
        if (row < Bsz) {
            float zi = zs[( 0 + j) * ZS_LD + r];
            float zf = zs[(16 + j) * ZS_LD + r];
            float zg = zs[(32 + j) * ZS_LD + r];
            float zo = zs[(48 + j) * ZS_LD + r];
            float ig = sigmoidf_(zi);
            float fg = sigmoidf_(zf);
            float gv = tanhf(zg);
            float og = sigmoidf_(zo);
            int idx = row * Hsz + jbase + j;
            float cn = fg * cp[idx] + ig * gv;
            cp[idx] = cn;
            float hn = og * tanhf(cn);
            hout[idx] = hn;
            if (seqp) seqp[idx] = hn;
        }
    }
}

// ---------------- K3: xz2 = seq @ W2 + b2  ([50000,256]x[256,1024]) ----------------
// grid (16 col-tiles, ceil(50000/128) row-tiles), 256 threads.
// CTA tile 128x64; per thread: 1 col x 32 rows (16 packed accumulators).
__global__ __launch_bounds__(256) void proj2(const float* __restrict__ W2,
                                             const float* __restrict__ b2) {
    extern __shared__ float smem[];
    float* At = smem;                   // [256][AT_LD] transposed A tile
    float* ws = smem + 256 * AT_LD;     // [256][64]
    const int tid = threadIdx.x;
    const int nbase = blockIdx.x * 64;
    const int mbase = blockIdx.y * PM;
    const int M = Tsz * Bsz;

    for (int idx = tid; idx < PM * 256; idx += 256) {
        int r = idx >> 8, k = idx & 255;
        int m = mbase + r;
        At[k * AT_LD + r] = (m < M) ? g_seq[(size_t)m * Hsz + k] : 0.f;
    }
    for (int idx = tid; idx < 256 * 64; idx += 256) {
        int k = idx >> 6, cc = idx & 63;
        ws[idx] = W2[k * G4 + nbase + cc];
    }
    __syncthreads();

    const int tx = tid & 63;
    const int ty = tid >> 6;
    const int r0 = ty * 32;
    unsigned long long acc[16];
    #pragma unroll
    for (int i = 0; i < 16; ++i) acc[i] = 0ull;
    const float* wl = ws + tx;
    const float* al = At + r0;
    #pragma unroll 2
    for (int k = 0; k < 256; ++k) {
        unsigned long long ub = pack_dup(wl[k * 64]);
        #pragma unroll
        for (int i = 0; i < 8; ++i) {
            ulonglong2 hv = *reinterpret_cast<const ulonglong2*>(al + k * AT_LD + 4 * i);
            ffma2(acc[2 * i],     hv.x, ub);
            ffma2(acc[2 * i + 1], hv.y, ub);
        }
    }
    float bb = b2[nbase + tx];
    #pragma unroll
    for (int p = 0; p < 16; ++p) {
        int rr = r0 + 4 * (p >> 1) + 2 * (p & 1);
        float lo, hi;
        unpack2(acc[p], lo, hi);
        int m0 = mbase + rr;
        if (m0 < M)     g_xz2[(size_t)m0 * G4 + nbase + tx]       = lo + bb;
        if (m0 + 1 < M) g_xz2[(size_t)(m0 + 1) * G4 + nbase + tx] = hi + bb;
    }
}

// ---------------- K5: dense + relu + dense + softmax ----------------
__global__ __launch_bounds__(256) void head(const float* __restrict__ Wd,
                                            const float* __restrict__ bd,
                                            const float* __restrict__ Ws,
                                            const float* __restrict__ bs,
                                            float* __restrict__ out) {
    __shared__ float hrow[Hsz];
    __shared__ float hid[Dsz];
    __shared__ float lbuf[Csz];
    __shared__ float ebuf[Csz];
    int b = blockIdx.x, tid = threadIdx.x;
    hrow[tid] = g_h2a[b * Hsz + tid];   // final h2 lives in buffer 'a' (T even)
    __syncthreads();
    if (tid < Dsz) {
        float s = bd[tid];
        #pragma unroll 8
        for (int k = 0; k < Hsz; ++k) s += hrow[k] * Wd[k * Dsz + tid];
        hid[tid] = fmaxf(s, 0.f);
    }
    __syncthreads();
    if (tid < Csz) {
        float s = bs[tid];
        for (int d = 0; d < Dsz; ++d) s += hid[d] * Ws[d * Csz + tid];
        lbuf[tid] = s;
    }
    __syncthreads();
    if (tid < Csz) {
        float m = lbuf[0];
        #pragma unroll
        for (int j = 1; j < Csz; ++j) m = fmaxf(m, lbuf[j]);
        ebuf[tid] = __expf(lbuf[tid] - m);
    }
    __syncthreads();
    if (tid < Csz) {
        float sum = 0.f;
        #pragma unroll
        for (int j = 0; j < Csz; ++j) sum += ebuf[j];
        out[b * Csz + tid] = ebuf[tid] / sum;
    }
}

// ---------------- launch ----------------
extern "C" void kernel_launch(void* const* d_in, const int* in_sizes, int n_in,
                              void* d_out, int out_size) {
    (void)in_sizes; (void)n_in; (void)out_size;
    const float* inputs = (const float*)d_in[0];
    const float* W1 = (const float*)d_in[1];
    const float* U1 = (const float*)d_in[2];
    const float* b1 = (const float*)d_in[3];
    const float* W2 = (const float*)d_in[4];
    const float* U2 = (const float*)d_in[5];
    const float* b2 = (const float*)d_in[6];
    const float* Wd = (const float*)d_in[7];
    const float* bd = (const float*)d_in[8];
    const float* Ws = (const float*)d_in[9];
    const float* bs = (const float*)d_in[10];
    float* out = (float*)d_out;
    (void)b1;

    const int SM_STEP = (256 * HST_LD + 256 * 64 + 64 * ZS_LD) * 4;   // ~110.8 KB
    const int SM_PROJ = (256 * AT_LD + 256 * 64) * 4;                 // ~200.7 KB
    cudaFuncSetAttribute(lstm_step, cudaFuncAttributeMaxDynamicSharedMemorySize, SM_STEP);
    cudaFuncSetAttribute(proj2,     cudaFuncAttributeMaxDynamicSharedMemorySize, SM_PROJ);

    zero_state<<<(Bsz * Hsz + 255) / 256, 256>>>();
    inproj1<<<Bsz * Tsz, 256>>>(inputs, W1, (const float*)d_in[3]);

    dim3 sg(16, (Bsz + 31) / 32);
    for (int t = 0; t < Tsz; ++t)
        lstm_step<<<sg, 256, SM_STEP>>>(t, 0, U1);

    proj2<<<dim3(16, (Tsz * Bsz + PM - 1) / PM), 256, SM_PROJ>>>(W2, b2);

    for (int t = 0; t < Tsz; ++t)
        lstm_step<<<sg, 256, SM_STEP>>>(t, 1, U2);

    head<<<Bsz, 256>>>(Wd, bd, Ws, bs, out);
}

// round 5
// speedup vs baseline: 1.4164x; 1.4046x over previous
#include <cuda_runtime.h>

#define Bsz 200
#define Tsz 250
#define Fsz 14
#define Hsz 256
#define G4  1024
#define Dsz 164
#define Csz 8
#define NCOLT 16
#define NROWT 9
#define RPT   24
#define ZS_LD 25
#define PM    128
#define AT_LD 132

__device__ float g_xz2[Tsz * Bsz * G4];
__device__ float g_seq[Tsz * Bsz * Hsz];
__device__ float g_h1a[Bsz * Hsz];
__device__ float g_h1b[Bsz * Hsz];
__device__ float g_c1 [Bsz * Hsz];
__device__ float g_h2a[Bsz * Hsz];
__device__ float g_h2b[Bsz * Hsz];
__device__ float g_c2 [Bsz * Hsz];
__device__ unsigned g_cnt [2][NROWT];
__device__ unsigned g_flag[2][NROWT];

__device__ __forceinline__ unsigned long long pack_dup(float u) {
    unsigned int uu = __float_as_uint(u);
    unsigned long long r;
    asm("mov.b64 %0, {%1, %1};" : "=l"(r) : "r"(uu));
    return r;
}
__device__ __forceinline__ void ffma2(unsigned long long& d, unsigned long long a, unsigned long long b) {
    asm("fma.rn.f32x2 %0, %1, %2, %0;" : "+l"(d) : "l"(a), "l"(b));
}
__device__ __forceinline__ void unpack2(unsigned long long v, float& lo, float& hi) {
    unsigned int l, h;
    asm("mov.b64 {%0, %1}, %2;" : "=r"(l), "=r"(h) : "l"(v));
    lo = __uint_as_float(l); hi = __uint_as_float(h);
}
__device__ __forceinline__ float sigmoidf_(float x) { return 1.0f / (1.0f + __expf(-x)); }

__global__ void zero_state() {
    int i = blockIdx.x * blockDim.x + threadIdx.x;
    if (i < Bsz * Hsz) { g_c1[i] = 0.f; g_c2[i] = 0.f; }
    if (i < 2 * NROWT) { ((unsigned*)g_cnt)[i] = 0u; ((unsigned*)g_flag)[i] = 0u; }
}

// persistent LSTM layer: grid (16,9)=144 CTAs, 256 thr, all 250 steps inside.
// CTA tile 24 rows x 16 h-cols (64 gate cols). thread: tx gate-col, 6 rows.
__global__ __launch_bounds__(256, 1) void lstm_layer(
    int layer, const float* __restrict__ U,
    const float* __restrict__ W1, const float* __restrict__ b1,
    const float* __restrict__ inputs)
{
    extern __shared__ float smem[];
    float* ust = smem;                    // [64][256] U strip, k-swizzled
    float* hst = ust + 64 * 256;          // [24][256] h tile, row-major
    float* zs  = hst + RPT * 256;         // [64][ZS_LD]
    float* w1s = zs + 64 * ZS_LD;         // [14][64]
    float* b1s = w1s + Fsz * 64;          // [64]
    float* xin = b1s + 64;                // [24][16]

    const int tid   = threadIdx.x;
    const int jbase = blockIdx.x * 16;
    const int grp   = blockIdx.y;
    const int rbase = grp * RPT;

    float* ha = layer ? g_h2a : g_h1a;
    float* hb = layer ? g_h2b : g_h1b;
    float* cp = layer ? g_c2  : g_c1;

    for (int idx = tid; idx < 64 * 256; idx += 256) {
        int k = idx >> 6, c = idx & 63;
        float u = U[k * G4 + ((c >> 4) << 8) + jbase + (c & 15)];
        ust[c * 256 + (k ^ ((c & 7) << 2))] = u;
    }
    if (layer == 0) {
        for (int idx = tid; idx < Fsz * 64; idx += 256) {
            int f = idx >> 6, c = idx & 63;
            w1s[idx] = W1[f * G4 + ((c >> 4) << 8) + jbase + (c & 15)];
        }
        if (tid < 64) b1s[tid] = b1[((tid >> 4) << 8) + jbase + (tid & 15)];
    }

    const int tx = tid & 63;
    const int ty = tid >> 6;
    const int r0 = ty * 6;
    const int xs = (tx & 7) << 2;
    const float* usl = ust + tx * 256;
    const float* hl  = hst + r0 * 256;
    const int col = ((tx >> 4) << 8) + jbase + (tx & 15);

    for (int t = 0; t < Tsz; ++t) {
        const float* hin  = (t & 1) ? hb : ha;
        float*       hout = (t & 1) ? ha : hb;

        if (t == 0) {
            for (int idx = tid; idx < RPT * 256; idx += 256) hst[idx] = 0.f;
        } else {
            for (int idx = tid; idx < RPT * 256; idx += 256) {
                int r = idx >> 8, k = idx & 255;
                int row = rbase + r;
                hst[idx] = (row < Bsz) ? __ldcg(hin + row * Hsz + k) : 0.f;
            }
        }
        if (layer == 0) {
            for (int idx = tid; idx < RPT * 16; idx += 256) {
                int r = idx >> 4, f = idx & 15;
                int row = rbase + r;
                xin[idx] = (f < Fsz && row < Bsz)
                         ? __ldg(inputs + ((size_t)row * Tsz + t) * Fsz + f) : 0.f;
            }
        }
        float xzv[6];
        if (layer) {
            const float* xzt = g_xz2 + (size_t)t * Bsz * G4;
            #pragma unroll
            for (int i = 0; i < 6; ++i) {
                int row = rbase + r0 + i;
                xzv[i] = (row < Bsz) ? __ldg(xzt + (size_t)row * G4 + col) : 0.f;
            }
        }
        __syncthreads();

        unsigned long long a0 = 0, a1 = 0, a2 = 0, a3 = 0, a4 = 0, a5 = 0;
        #pragma unroll 4
        for (int k = 0; k < 256; k += 4) {
            ulonglong2 uv = *reinterpret_cast<const ulonglong2*>(usl + (k ^ xs));
            ulonglong2 h0 = *reinterpret_cast<const ulonglong2*>(hl + 0 * 256 + k);
            ulonglong2 h1 = *reinterpret_cast<const ulonglong2*>(hl + 1 * 256 + k);
            ulonglong2 h2 = *reinterpret_cast<const ulonglong2*>(hl + 2 * 256 + k);
            ulonglong2 h3 = *reinterpret_cast<const ulonglong2*>(hl + 3 * 256 + k);
            ulonglong2 h4 = *reinterpret_cast<const ulonglong2*>(hl + 4 * 256 + k);
            ulonglong2 h5 = *reinterpret_cast<const ulonglong2*>(hl + 5 * 256 + k);
            ffma2(a0, h0.x, uv.x); ffma2(a1, h1.x, uv.x); ffma2(a2, h2.x, uv.x);
            ffma2(a3, h3.x, uv.x); ffma2(a4, h4.x, uv.x); ffma2(a5, h5.x, uv.x);
            ffma2(a0, h0.y, uv.y); ffma2(a1, h1.y, uv.y); ffma2(a2, h2.y, uv.y);
            ffma2(a3, h3.y, uv.y); ffma2(a4, h4.y, uv.y); ffma2(a5, h5.y, uv.y);
        }
        float z[6];
        { float lo, hi;
          unpack2(a0, lo, hi); z[0] = lo + hi;
          unpack2(a1, lo, hi); z[1] = lo + hi;
          unpack2(a2, lo, hi); z[2] = lo + hi;
          unpack2(a3, lo, hi); z[3] = lo + hi;
          unpack2(a4, lo, hi); z[4] = lo + hi;
          unpack2(a5, lo, hi); z[5] = lo + hi; }

        if (layer == 0) {
            float bias = b1s[tx];
            #pragma unroll
            for (int i = 0; i < 6; ++i) {
                float s = bias;
                #pragma unroll
                for (int f = 0; f < Fsz; ++f)
                    s += xin[(r0 + i) * 16 + f] * w1s[f * 64 + tx];
                z[i] += s;
            }
        } else {
            #pragma unroll
            for (int i = 0; i < 6; ++i) z[i] += xzv[i];
        }
        #pragma unroll
        for (int i = 0; i < 6; ++i) zs[tx * ZS_LD + r0 + i] = z[i];
        __syncthreads();

        for (int cell = tid; cell < RPT * 16; cell += 256) {
            int j = cell & 15, r = cell >> 4;
            int row = rbase + r;
            if (row < Bsz) {
                float zi = zs[( 0 + j) * ZS_LD + r];
                float zf = zs[(16 + j) * ZS_LD + r];
                float zg = zs[(32 + j) * ZS_LD + r];
                float zo = zs[(48 + j) * ZS_LD + r];
                float ig = sigmoidf_(zi), fg = sigmoidf_(zf);
                float gv = tanhf(zg),     og = sigmoidf_(zo);
                int gidx = row * Hsz + jbase + j;
                float cn = fg * cp[gidx] + ig * gv;
                cp[gidx] = cn;
                float hn = og * tanhf(cn);
                hout[gidx] = hn;
                if (layer == 0) g_seq[(size_t)t * Bsz * Hsz + gidx] = hn;
            }
        }

        __syncthreads();
        if (tid == 0) {
            __threadfence();
            unsigned n = atomicAdd(&g_cnt[layer][grp], 1u);
            if (n == NCOLT - 1) {
                g_cnt[layer][grp] = 0u;
                __threadfence();
                atomicExch(&g_flag[layer][grp], (unsigned)(t + 1));
            } else {
                volatile unsigned* fl = &g_flag[layer][grp];
                while (*fl < (unsigned)(t + 1)) { }
            }
            __threadfence();
        }
        __syncthreads();
    }
}

__global__ __launch_bounds__(256) void proj2(const float* __restrict__ W2,
                                             const float* __restrict__ b2) {
    extern __shared__ float smem[];
    float* At = smem;
    float* ws = smem + 256 * AT_LD;
    const int tid = threadIdx.x;
    const int nbase = blockIdx.x * 64;
    const int mbase = blockIdx.y * PM;
    const int M = Tsz * Bsz;

    for (int idx = tid; idx < PM * 256; idx += 256) {
        int r = idx >> 8, k = idx & 255;
        int m = mbase + r;
        At[k * AT_LD + r] = (m < M) ? g_seq[(size_t)m * Hsz + k] : 0.f;
    }
    for (int idx = tid; idx < 256 * 64; idx += 256) {
        int k = idx >> 6, cc = idx & 63;
        ws[idx] = W2[k * G4 + nbase + cc];
    }
    __syncthreads();

    const int tx = tid & 63;
    const int ty = tid >> 6;
    const int r0 = ty * 32;
    unsigned long long acc[16];
    #pragma unroll
    for (int i = 0; i < 16; ++i) acc[i] = 0ull;
    const float* wl = ws + tx;
    const float* al = At + r0;
    #pragma unroll 2
    for (int k = 0; k < 256; ++k) {
        unsigned long long ub = pack_dup(wl[k * 64]);
        #pragma unroll
        for (int i = 0; i < 8; ++i) {
            ulonglong2 hv = *reinterpret_cast<const ulonglong2*>(al + k * AT_LD + 4 * i);
            ffma2(acc[2 * i],     hv.x, ub);
            ffma2(acc[2 * i + 1], hv.y, ub);
        }
    }
    float bb = b2[nbase + tx];
    #pragma unroll
    for (int p = 0; p < 16; ++p) {
        int rr = r0 + 4 * (p >> 1) + 2 * (p & 1);
        float lo, hi;
        unpack2(acc[p], lo, hi);
        int m0 = mbase + rr;
        if (m0 < M)     g_xz2[(size_t)m0 * G4 + nbase + tx]       = lo + bb;
        if (m0 + 1 < M) g_xz2[(size_t)(m0 + 1) * G4 + nbase + tx] = hi + bb;
    }
}

__global__ __launch_bounds__(256) void head(const float* __restrict__ Wd,
                                            const float* __restrict__ bd,
                                            const float* __restrict__ Ws,
                                            const float* __restrict__ bs,
                                            float* __restrict__ out) {
    __shared__ float hrow[Hsz];
    __shared__ float hid[Dsz];
    __shared__ float lbuf[Csz];
    __shared__ float ebuf[Csz];
    int b = blockIdx.x, tid = threadIdx.x;
    hrow[tid] = g_h2a[b * Hsz + tid];   // t=249 odd -> buffer 'a'
    __syncthreads();
    if (tid < Dsz) {
        float s = bd[tid];
        #pragma unroll 8
        for (int k = 0; k < Hsz; ++k) s += hrow[k] * Wd[k * Dsz + tid];
        hid[tid] = fmaxf(s, 0.f);
    }
    __syncthreads();
    if (tid < Csz) {
        float s = bs[tid];
        for (int d = 0; d < Dsz; ++d) s += hid[d] * Ws[d * Csz + tid];
        lbuf[tid] = s;
    }
    __syncthreads();
    if (tid < Csz) {
        float m = lbuf[0];
        #pragma unroll
        for (int j = 1; j < Csz; ++j) m = fmaxf(m, lbuf[j]);
        ebuf[tid] = __expf(lbuf[tid] - m);
    }
    __syncthreads();
    if (tid < Csz) {
        float sum = 0.f;
        #pragma unroll
        for (int j = 0; j < Csz; ++j) sum += ebuf[j];
        out[b * Csz + tid] = ebuf[tid] / sum;
    }
}

extern "C" void kernel_launch(void* const* d_in, const int* in_sizes, int n_in,
                              void* d_out, int out_size) {
    (void)in_sizes; (void)n_in; (void)out_size;
    const float* inputs = (const float*)d_in[0];
    const float* W1 = (const float*)d_in[1];
    const float* U1 = (const float*)d_in[2];
    const float* b1 = (const float*)d_in[3];
    const float* W2 = (const float*)d_in[4];
    const float* U2 = (const float*)d_in[5];
    const float* b2 = (const float*)d_in[6];
    const float* Wd = (const float*)d_in[7];
    const float* bd = (const float*)d_in[8];
    const float* Ws = (const float*)d_in[9];
    const float* bs = (const float*)d_in[10];
    float* out = (float*)d_out;

    const int SM_STEP = (64 * 256 + RPT * 256 + 64 * ZS_LD + Fsz * 64 + 64 + RPT * 16) * 4;
    const int SM_PROJ = (256 * AT_LD + 256 * 64) * 4;
    cudaFuncSetAttribute(lstm_layer, cudaFuncAttributeMaxDynamicSharedMemorySize, SM_STEP);
    cudaFuncSetAttribute(proj2,      cudaFuncAttributeMaxDynamicSharedMemorySize, SM_PROJ);

    zero_state<<<(Bsz * Hsz + 255) / 256, 256>>>();

    dim3 lg(NCOLT, NROWT);
    lstm_layer<<<lg, 256, SM_STEP>>>(0, U1, W1, b1, inputs);
    proj2<<<dim3(16, (Tsz * Bsz + PM - 1) / PM), 256, SM_PROJ>>>(W2, b2);
    lstm_layer<<<lg, 256, SM_STEP>>>(1, U2, W1, b1, inputs);
    head<<<Bsz, 256>>>(Wd, bd, Ws, bs, out);
}

// round 10
// speedup vs baseline: 1.8656x; 1.3172x over previous
#include <cuda_runtime.h>

#define Bsz 200
#define Tsz 250
#define Fsz 14
#define Hsz 256
#define G4  1024
#define Dsz 164
#define Csz 8
#define NCOLT 16
#define NROWT 9
#define RPT   24
#define ZS_LD 25
#define P2M   128

__device__ float g_xz2[Tsz * Bsz * G4];
__device__ float g_seq[Tsz * Bsz * Hsz];
__device__ float g_h1a[Bsz * Hsz];
__device__ float g_h1b[Bsz * Hsz];
__device__ float g_h2a[Bsz * Hsz];
__device__ float g_h2b[Bsz * Hsz];
__device__ unsigned g_cnt [2][NROWT];
__device__ unsigned g_flag[2][NROWT];

__device__ __forceinline__ void ffma2(unsigned long long& d, unsigned long long a, unsigned long long b) {
    asm("fma.rn.f32x2 %0, %1, %2, %0;" : "+l"(d) : "l"(a), "l"(b));
}
__device__ __forceinline__ void unpack2(unsigned long long v, float& lo, float& hi) {
    unsigned int l, h;
    asm("mov.b64 {%0, %1}, %2;" : "=r"(l), "=r"(h) : "l"(v));
    lo = __uint_as_float(l); hi = __uint_as_float(h);
}
// ACCURATE activations — the recurrence compounds error over 250 steps.
// Fast __expf-based tanh was measured at rel_err 1.2e-3 (FAIL); these give 6.9e-8.
__device__ __forceinline__ float sigmoidf_(float x) {
    return 1.0f / (1.0f + __expf(-x));
}
__device__ __forceinline__ float tanh_acc(float x) { return tanhf(x); }

__global__ void zero_state() {
    int i = blockIdx.x * blockDim.x + threadIdx.x;
    if (i < 2 * NROWT) { ((unsigned*)g_cnt)[i] = 0u; ((unsigned*)g_flag)[i] = 0u; }
}

// persistent LSTM layer: grid (16,9)=144 CTAs, 256 thr, all 250 steps inside.
// CTA tile 24 rows x 16 h-cols (64 gate cols). thread: tx gate-col, 6 rows.
__global__ __launch_bounds__(256, 1) void lstm_layer(
    int layer, const float* __restrict__ U,
    const float* __restrict__ W1, const float* __restrict__ b1,
    const float* __restrict__ inputs)
{
    extern __shared__ float smem[];
    float* ust = smem;                    // [64][256] U strip, k-swizzled
    float* hst = ust + 64 * 256;          // [24][256] h tile, row-major
    float* zs  = hst + RPT * 256;         // [64][ZS_LD]
    float* w1s = zs + 64 * ZS_LD;         // [14][64]
    float* b1s = w1s + Fsz * 64;          // [64]
    float* xin = b1s + 64;                // [24][16]
    __shared__ float csh[RPT * 16];       // cell state, CTA-private

    const int tid   = threadIdx.x;
    const int jbase = blockIdx.x * 16;
    const int grp   = blockIdx.y;
    const int rbase = grp * RPT;

    float* ha = layer ? g_h2a : g_h1a;
    float* hb = layer ? g_h2b : g_h1b;

    // ---- one-time staging: U strip, batched 8x8 ----
    #pragma unroll
    for (int bb = 0; bb < 8; ++bb) {
        float tf[8];
        #pragma unroll
        for (int i = 0; i < 8; ++i) {
            int idx = tid + (bb * 8 + i) * 256;
            int k = idx >> 6, c = idx & 63;
            tf[i] = __ldg(U + k * G4 + ((c >> 4) << 8) + jbase + (c & 15));
        }
        #pragma unroll
        for (int i = 0; i < 8; ++i) {
            int idx = tid + (bb * 8 + i) * 256;
            int k = idx >> 6, c = idx & 63;
            ust[c * 256 + (k ^ ((c & 7) << 2))] = tf[i];
        }
    }
    if (layer == 0) {
        for (int idx = tid; idx < Fsz * 64; idx += 256) {
            int f = idx >> 6, c = idx & 63;
            w1s[idx] = W1[f * G4 + ((c >> 4) << 8) + jbase + (c & 15)];
        }
        if (tid < 64) b1s[tid] = b1[((tid >> 4) << 8) + jbase + (tid & 15)];
    }
    csh[tid] = 0.f;
    if (tid < RPT * 16 - 256) csh[256 + tid] = 0.f;

    const int tx = tid & 63;
    const int ty = tid >> 6;
    const int r0 = ty * 6;
    const int xs = (tx & 7) << 2;
    const float* usl = ust + tx * 256;
    const float* hl  = hst + r0 * 256;
    const int col = ((tx >> 4) << 8) + jbase + (tx & 15);

    // xin prefetch indices
    const int xr0 = tid >> 4,  xf0 = tid & 15;
    const int xr1 = (256 + tid) >> 4;

    for (int t = 0; t < Tsz; ++t) {
        const float* hin  = (t & 1) ? hb : ha;
        float*       hout = (t & 1) ? ha : hb;

        // ---- prefetch (regs, independent of h(t)) ----
        float xp0 = 0.f, xp1 = 0.f;
        float xzv[6];
        if (layer == 0) {
            { int row = rbase + xr0;
              if (row < Bsz && xf0 < Fsz) xp0 = __ldg(inputs + ((size_t)row * Tsz + t) * Fsz + xf0); }
            if (tid < 128) {
                int row = rbase + xr1;
                if (row < Bsz && xf0 < Fsz) xp1 = __ldg(inputs + ((size_t)row * Tsz + t) * Fsz + xf0);
            }
        } else {
            const float* xzt = g_xz2 + (size_t)t * Bsz * G4;
            #pragma unroll
            for (int i = 0; i < 6; ++i) {
                int row = rbase + r0 + i;
                xzv[i] = (row < Bsz) ? __ldg(xzt + (size_t)row * G4 + col) : 0.f;
            }
        }

        // ---- wait for h(t) ----
        if (t > 0) {
            if (tid == 0) {
                volatile unsigned* fl = &g_flag[layer][grp];
                while (*fl < (unsigned)t) { }
                __threadfence();
            }
        }
        __syncthreads();

        // ---- stage h tile (batched float4) ----
        if (t == 0) {
            #pragma unroll
            for (int i = 0; i < 6; ++i)
                ((float4*)hst)[tid + i * 256] = make_float4(0.f, 0.f, 0.f, 0.f);
        } else {
            const float4* hin4 = (const float4*)hin;
            float4 tf[6];
            #pragma unroll
            for (int i = 0; i < 6; ++i) {
                int idx = tid + i * 256;
                int r = idx >> 6, k4 = idx & 63;
                int row = rbase + r;
                tf[i] = (row < Bsz) ? __ldcg(hin4 + (size_t)row * 64 + k4)
                                    : make_float4(0.f, 0.f, 0.f, 0.f);
            }
            #pragma unroll
            for (int i = 0; i < 6; ++i)
                ((float4*)hst)[tid + i * 256] = tf[i];
        }
        if (layer == 0) {
            xin[tid] = xp0;
            if (tid < 128) xin[256 + tid] = xp1;
        }
        __syncthreads();

        // ---- recurrent GEMM: even/odd-k packed f32x2 ----
        unsigned long long a0 = 0, a1 = 0, a2 = 0, a3 = 0, a4 = 0, a5 = 0;
        #pragma unroll 4
        for (int k = 0; k < 256; k += 4) {
            ulonglong2 uv = *reinterpret_cast<const ulonglong2*>(usl + (k ^ xs));
            ulonglong2 h0 = *reinterpret_cast<const ulonglong2*>(hl + 0 * 256 + k);
            ulonglong2 h1 = *reinterpret_cast<const ulonglong2*>(hl + 1 * 256 + k);
            ulonglong2 h2 = *reinterpret_cast<const ulonglong2*>(hl + 2 * 256 + k);
            ulonglong2 h3 = *reinterpret_cast<const ulonglong2*>(hl + 3 * 256 + k);
            ulonglong2 h4 = *reinterpret_cast<const ulonglong2*>(hl + 4 * 256 + k);
            ulonglong2 h5 = *reinterpret_cast<const ulonglong2*>(hl + 5 * 256 + k);
            ffma2(a0, h0.x, uv.x); ffma2(a1, h1.x, uv.x); ffma2(a2, h2.x, uv.x);
            ffma2(a3, h3.x, uv.x); ffma2(a4, h4.x, uv.x); ffma2(a5, h5.x, uv.x);
            ffma2(a0, h0.y, uv.y); ffma2(a1, h1.y, uv.y); ffma2(a2, h2.y, uv.y);
            ffma2(a3, h3.y, uv.y); ffma2(a4, h4.y, uv.y); ffma2(a5, h5.y, uv.y);
        }
        float z[6];
        { float lo, hi;
          unpack2(a0, lo, hi); z[0] = lo + hi;
          unpack2(a1, lo, hi); z[1] = lo + hi;
          unpack2(a2, lo, hi); z[2] = lo + hi;
          unpack2(a3, lo, hi); z[3] = lo + hi;
          unpack2(a4, lo, hi); z[4] = lo + hi;
          unpack2(a5, lo, hi); z[5] = lo + hi; }

        if (layer == 0) {
            float w1r[Fsz];
            #pragma unroll
            for (int f = 0; f < Fsz; ++f) w1r[f] = w1s[f * 64 + tx];
            float bias = b1s[tx];
            #pragma unroll
            for (int i = 0; i < 6; ++i) {
                float s = bias;
                #pragma unroll
                for (int f = 0; f < Fsz; ++f)
                    s += xin[(r0 + i) * 16 + f] * w1r[f];
                z[i] += s;
            }
        } else {
            #pragma unroll
            for (int i = 0; i < 6; ++i) z[i] += xzv[i];
        }
        #pragma unroll
        for (int i = 0; i < 6; ++i) zs[tx * ZS_LD + r0 + i] = z[i];
        __syncthreads();

        // ---- gate combine (c in SMEM, accurate activations) ----
        for (int cell = tid; cell < RPT * 16; cell += 256) {
            int j = cell & 15, r = cell >> 4;
            int row = rbase + r;
            if (row < Bsz) {
                float zi = zs[( 0 + j) * ZS_LD + r];
                float zf = zs[(16 + j) * ZS_LD + r];
                float zg = zs[(32 + j) * ZS_LD + r];
                float zo = zs[(48 + j) * ZS_LD + r];
                float ig = sigmoidf_(zi), fg = sigmoidf_(zf);
                float gv = tanh_acc(zg),  og = sigmoidf_(zo);
                float cn = fg * csh[cell] + ig * gv;
                csh[cell] = cn;
                float hn = og * tanh_acc(cn);
                int gidx = row * Hsz + jbase + j;
                hout[gidx] = hn;
                if (layer == 0) g_seq[(size_t)t * Bsz * Hsz + gidx] = hn;
            }
        }

        // ---- release ----
        __syncthreads();
        if (tid == 0) {
            __threadfence();
            unsigned n = atomicAdd(&g_cnt[layer][grp], 1u);
            if (n == NCOLT - 1) {
                g_cnt[layer][grp] = 0u;
                __threadfence();
                atomicExch(&g_flag[layer][grp], (unsigned)(t + 1));
            }
        }
    }
}

// proj2: xz2 = seq @ W2 + b2  ([50000,256]x[256,1024])
__global__ __launch_bounds__(256, 1) void proj2(const float* __restrict__ W2,
                                                const float* __restrict__ b2) {
    extern __shared__ float sm[];
    float* ws = sm;                 // [64][256] swizzled W strip
    float* At = sm + 64 * 256;      // [128][256] row-major A tile
    const int tid = threadIdx.x;
    const int nbase = blockIdx.x * 64;
    const int mbase = blockIdx.y * P2M;
    const int M = Tsz * Bsz;

    #pragma unroll
    for (int bb = 0; bb < 8; ++bb) {
        float tf[8];
        #pragma unroll
        for (int i = 0; i < 8; ++i) {
            int idx = tid + (bb * 8 + i) * 256;
            int k = idx >> 6, c = idx & 63;
            tf[i] = __ldg(W2 + k * G4 + nbase + c);
        }
        #pragma unroll
        for (int i = 0; i < 8; ++i) {
            int idx = tid + (bb * 8 + i) * 256;
            int k = idx >> 6, c = idx & 63;
            ws[c * 256 + (k ^ ((c & 7) << 2))] = tf[i];
        }
    }
    {
        const float4* sq4 = (const float4*)g_seq;
        float4* At4 = (float4*)At;
        #pragma unroll
        for (int bb = 0; bb < 4; ++bb) {
            float4 tf[8];
            #pragma unroll
            for (int i = 0; i < 8; ++i) {
                int idx = tid + (bb * 8 + i) * 256;
                int r = idx >> 6, k4 = idx & 63;
                int m = mbase + r;
                tf[i] = (m < M) ? __ldg(sq4 + (size_t)m * 64 + k4)
                                : make_float4(0.f, 0.f, 0.f, 0.f);
            }
            #pragma unroll
            for (int i = 0; i < 8; ++i)
                At4[tid + (bb * 8 + i) * 256] = tf[i];
        }
    }
    __syncthreads();

    const int tx = tid & 63;
    const int ty = tid >> 6;
    const int r0 = ty * 32;
    const int xs = (tx & 7) << 2;
    const float* wsl = ws + tx * 256;
    const float* al  = At + r0 * 256;

    unsigned long long acc[32];
    #pragma unroll
    for (int i = 0; i < 32; ++i) acc[i] = 0ull;

    #pragma unroll 1
    for (int k = 0; k < 256; k += 4) {
        ulonglong2 uv = *reinterpret_cast<const ulonglong2*>(wsl + (k ^ xs));
        #pragma unroll
        for (int i = 0; i < 32; ++i) {
            ulonglong2 hv = *reinterpret_cast<const ulonglong2*>(al + i * 256 + k);
            ffma2(acc[i], hv.x, uv.x);
            ffma2(acc[i], hv.y, uv.y);
        }
    }
    float bb2 = b2[nbase + tx];
    #pragma unroll
    for (int i = 0; i < 32; ++i) {
        int m = mbase + r0 + i;
        if (m < M) {
            float lo, hi;
            unpack2(acc[i], lo, hi);
            g_xz2[(size_t)m * G4 + nbase + tx] = lo + hi + bb2;
        }
    }
}

__global__ __launch_bounds__(256) void head(const float* __restrict__ Wd,
                                            const float* __restrict__ bd,
                                            const float* __restrict__ Ws,
                                            const float* __restrict__ bs,
                                            float* __restrict__ out) {
    __shared__ float hrow[Hsz];
    __shared__ float hid[Dsz];
    __shared__ float lbuf[Csz];
    __shared__ float ebuf[Csz];
    int b = blockIdx.x, tid = threadIdx.x;
    hrow[tid] = g_h2a[b * Hsz + tid];   // t=249 odd -> buffer 'a'
    __syncthreads();
    if (tid < Dsz) {
        float s = bd[tid];
        #pragma unroll 8
        for (int k = 0; k < Hsz; ++k) s += hrow[k] * Wd[k * Dsz + tid];
        hid[tid] = fmaxf(s, 0.f);
    }
    __syncthreads();
    if (tid < Csz) {
        float s = bs[tid];
        for (int d = 0; d < Dsz; ++d) s += hid[d] * Ws[d * Csz + tid];
        lbuf[tid] = s;
    }
    __syncthreads();
    if (tid < Csz) {
        float m = lbuf[0];
        #pragma unroll
        for (int j = 1; j < Csz; ++j) m = fmaxf(m, lbuf[j]);
        ebuf[tid] = __expf(lbuf[tid] - m);
    }
    __syncthreads();
    if (tid < Csz) {
        float sum = 0.f;
        #pragma unroll
        for (int j = 0; j < Csz; ++j) sum += ebuf[j];
        out[b * Csz + tid] = ebuf[tid] / sum;
    }
}

extern "C" void kernel_launch(void* const* d_in, const int* in_sizes, int n_in,
                              void* d_out, int out_size) {
    (void)in_sizes; (void)n_in; (void)out_size;
    const float* inputs = (const float*)d_in[0];
    const float* W1 = (const float*)d_in[1];
    const float* U1 = (const float*)d_in[2];
    const float* b1 = (const float*)d_in[3];
    const float* W2 = (const float*)d_in[4];
    const float* U2 = (const float*)d_in[5];
    const float* b2 = (const float*)d_in[6];
    const float* Wd = (const float*)d_in[7];
    const float* bd = (const float*)d_in[8];
    const float* Ws = (const float*)d_in[9];
    const float* bs = (const float*)d_in[10];
    float* out = (float*)d_out;

    // pad lstm smem to 120KB so only 1 CTA/SM fits (guarantees 144-CTA co-residency)
    const int SM_STEP = 120 * 1024;
    const int SM_PROJ = (64 * 256 + P2M * 256) * 4;   // 192KB
    cudaFuncSetAttribute(lstm_layer, cudaFuncAttributeMaxDynamicSharedMemorySize, SM_STEP);
    cudaFuncSetAttribute(proj2,      cudaFuncAttributeMaxDynamicSharedMemorySize, SM_PROJ);

    zero_state<<<1, 32>>>();

    dim3 lg(NCOLT, NROWT);
    lstm_layer<<<lg, 256, SM_STEP>>>(0, U1, W1, b1, inputs);
    proj2<<<dim3(16, (Tsz * Bsz + P2M - 1) / P2M), 256, SM_PROJ>>>(W2, b2);
    lstm_layer<<<lg, 256, SM_STEP>>>(1, U2, W1, b1, inputs);
    head<<<Bsz, 256>>>(Wd, bd, Ws, bs, out);
}

// round 11
// speedup vs baseline: 1.9234x; 1.0309x over previous
#include <cuda_runtime.h>

#define Bsz 200
#define Tsz 250
#define Fsz 14
#define Hsz 256
#define G4  1024
#define Dsz 164
#define Csz 8
#define NCOLT 16
#define NROWT 9
#define RPT   24
#define ZS_LD 25
#define P2M   128

__device__ float g_xz2[Tsz * Bsz * G4];
__device__ float g_seq[Tsz * Bsz * Hsz];
__device__ float g_h1a[Bsz * Hsz];
__device__ float g_h1b[Bsz * Hsz];
__device__ float g_h2a[Bsz * Hsz];
__device__ float g_h2b[Bsz * Hsz];
__device__ unsigned g_cnt [2][NROWT];
__device__ unsigned g_flag[2][NROWT];

__device__ __forceinline__ void ffma2(unsigned long long& d, unsigned long long a, unsigned long long b) {
    asm("fma.rn.f32x2 %0, %1, %2, %0;" : "+l"(d) : "l"(a), "l"(b));
}
__device__ __forceinline__ void unpack2(unsigned long long v, float& lo, float& hi) {
    unsigned int l, h;
    asm("mov.b64 {%0, %1}, %2;" : "=r"(l), "=r"(h) : "l"(v));
    lo = __uint_as_float(l); hi = __uint_as_float(h);
}
// ACCURATE activations — the recurrence compounds error over 250 steps.
// Fast __expf tanh measured at rel_err 1.2e-3 (FAIL); these give 6.9e-8.
__device__ __forceinline__ float sigmoidf_(float x) {
    return 1.0f / (1.0f + __expf(-x));
}
__device__ __forceinline__ float tanh_acc(float x) { return tanhf(x); }

__global__ void zero_state() {
    int i = blockIdx.x * blockDim.x + threadIdx.x;
    if (i < 2 * NROWT) { ((unsigned*)g_cnt)[i] = 0u; ((unsigned*)g_flag)[i] = 0u; }
}

// persistent LSTM layer: grid (16,9)=144 CTAs, 512 thr, all 250 steps inside.
// CTA tile 24 rows x 16 h-cols (64 gate cols). 2 k-groups of 256 threads:
// group kg handles k in [kg*128, kg*128+128); partials summed via zs[2].
__global__ __launch_bounds__(512, 1) void lstm_layer(
    int layer, const float* __restrict__ U,
    const float* __restrict__ W1, const float* __restrict__ b1,
    const float* __restrict__ inputs)
{
    extern __shared__ float smem[];
    float* ust = smem;                    // [64][256] U strip, k-swizzled
    float* hst = ust + 64 * 256;          // [24][256] h tile, row-major
    float* zs0 = hst + RPT * 256;         // [64][ZS_LD] partial (kg=0)
    float* zs1 = zs0 + 64 * ZS_LD;        // [64][ZS_LD] partial (kg=1)
    float* w1s = zs1 + 64 * ZS_LD;        // [14][64]
    float* b1s = w1s + Fsz * 64;          // [64]
    float* xin = b1s + 64;                // [24][16]
    __shared__ float csh[RPT * 16];       // cell state, CTA-private

    const int tid   = threadIdx.x;
    const int tid8  = tid & 255;
    const int kg    = tid >> 8;
    const int jbase = blockIdx.x * 16;
    const int grp   = blockIdx.y;
    const int rbase = grp * RPT;

    float* ha = layer ? g_h2a : g_h1a;
    float* hb = layer ? g_h2b : g_h1b;

    // ---- one-time staging: U strip (16384 floats, 32/thread, batched) ----
    #pragma unroll
    for (int bb = 0; bb < 4; ++bb) {
        float tf[8];
        #pragma unroll
        for (int i = 0; i < 8; ++i) {
            int idx = tid + (bb * 8 + i) * 512;
            int k = idx >> 6, c = idx & 63;
            tf[i] = __ldg(U + k * G4 + ((c >> 4) << 8) + jbase + (c & 15));
        }
        #pragma unroll
        for (int i = 0; i < 8; ++i) {
            int idx = tid + (bb * 8 + i) * 512;
            int k = idx >> 6, c = idx & 63;
            ust[c * 256 + (k ^ ((c & 7) << 2))] = tf[i];
        }
    }
    if (layer == 0) {
        for (int idx = tid; idx < Fsz * 64; idx += 512) {
            int f = idx >> 6, c = idx & 63;
            w1s[idx] = W1[f * G4 + ((c >> 4) << 8) + jbase + (c & 15)];
        }
        if (tid < 64) b1s[tid] = b1[((tid >> 4) << 8) + jbase + (tid & 15)];
    }
    if (tid < RPT * 16) csh[tid] = 0.f;

    const int tx = tid8 & 63;
    const int ty = tid8 >> 6;
    const int r0 = ty * 6;
    const int xs = (tx & 7) << 2;
    const int kbase = kg * 128;
    const float* usl = ust + tx * 256 + kbase;
    const float* hl  = hst + r0 * 256 + kbase;
    float* zsw = (kg ? zs1 : zs0) + tx * ZS_LD + r0;
    const int col = ((tx >> 4) << 8) + jbase + (tx & 15);

    // layer-0 xin prefetch mapping (one cell per thread, tid<384)
    const int xr = tid >> 4, xf = tid & 15;

    for (int t = 0; t < Tsz; ++t) {
        const float* hin  = (t & 1) ? hb : ha;
        float*       hout = (t & 1) ? ha : hb;

        // ---- prefetch (regs, independent of h(t)) ----
        float xp = 0.f;
        float xzv[6];
        if (layer == 0) {
            if (tid < RPT * 16) {
                int row = rbase + xr;
                if (row < Bsz && xf < Fsz)
                    xp = __ldg(inputs + ((size_t)row * Tsz + t) * Fsz + xf);
            }
        } else if (kg == 0) {
            const float* xzt = g_xz2 + (size_t)t * Bsz * G4;
            #pragma unroll
            for (int i = 0; i < 6; ++i) {
                int row = rbase + r0 + i;
                xzv[i] = (row < Bsz) ? __ldg(xzt + (size_t)row * G4 + col) : 0.f;
            }
        }

        // ---- wait for h(t) ----
        if (t > 0) {
            if (tid == 0) {
                volatile unsigned* fl = &g_flag[layer][grp];
                while (*fl < (unsigned)t) { }
                __threadfence();
            }
        }
        __syncthreads();

        // ---- stage h tile (1536 float4, 3/thread, batched) ----
        if (t == 0) {
            #pragma unroll
            for (int i = 0; i < 3; ++i)
                ((float4*)hst)[tid + i * 512] = make_float4(0.f, 0.f, 0.f, 0.f);
        } else {
            const float4* hin4 = (const float4*)hin;
            float4 tf[3];
            #pragma unroll
            for (int i = 0; i < 3; ++i) {
                int idx = tid + i * 512;
                int r = idx >> 6, k4 = idx & 63;
                int row = rbase + r;
                tf[i] = (row < Bsz) ? __ldcg(hin4 + (size_t)row * 64 + k4)
                                    : make_float4(0.f, 0.f, 0.f, 0.f);
            }
            #pragma unroll
            for (int i = 0; i < 3; ++i)
                ((float4*)hst)[tid + i * 512] = tf[i];
        }
        if (layer == 0 && tid < RPT * 16) xin[tid] = xp;
        __syncthreads();

        // ---- recurrent GEMM (this k-half): even/odd-k packed f32x2 ----
        unsigned long long a0 = 0, a1 = 0, a2 = 0, a3 = 0, a4 = 0, a5 = 0;
        #pragma unroll 4
        for (int k = 0; k < 128; k += 4) {
            ulonglong2 uv = *reinterpret_cast<const ulonglong2*>(usl + (k ^ xs));
            ulonglong2 h0 = *reinterpret_cast<const ulonglong2*>(hl + 0 * 256 + k);
            ulonglong2 h1 = *reinterpret_cast<const ulonglong2*>(hl + 1 * 256 + k);
            ulonglong2 h2 = *reinterpret_cast<const ulonglong2*>(hl + 2 * 256 + k);
            ulonglong2 h3 = *reinterpret_cast<const ulonglong2*>(hl + 3 * 256 + k);
            ulonglong2 h4 = *reinterpret_cast<const ulonglong2*>(hl + 4 * 256 + k);
            ulonglong2 h5 = *reinterpret_cast<const ulonglong2*>(hl + 5 * 256 + k);
            ffma2(a0, h0.x, uv.x); ffma2(a1, h1.x, uv.x); ffma2(a2, h2.x, uv.x);
            ffma2(a3, h3.x, uv.x); ffma2(a4, h4.x, uv.x); ffma2(a5, h5.x, uv.x);
            ffma2(a0, h0.y, uv.y); ffma2(a1, h1.y, uv.y); ffma2(a2, h2.y, uv.y);
            ffma2(a3, h3.y, uv.y); ffma2(a4, h4.y, uv.y); ffma2(a5, h5.y, uv.y);
        }
        float z[6];
        { float lo, hi;
          unpack2(a0, lo, hi); z[0] = lo + hi;
          unpack2(a1, lo, hi); z[1] = lo + hi;
          unpack2(a2, lo, hi); z[2] = lo + hi;
          unpack2(a3, lo, hi); z[3] = lo + hi;
          unpack2(a4, lo, hi); z[4] = lo + hi;
          unpack2(a5, lo, hi); z[5] = lo + hi; }

        // kg=0 folds in the input-path contribution
        if (kg == 0) {
            if (layer == 0) {
                float w1r[Fsz];
                #pragma unroll
                for (int f = 0; f < Fsz; ++f) w1r[f] = w1s[f * 64 + tx];
                float bias = b1s[tx];
                #pragma unroll
                for (int i = 0; i < 6; ++i) {
                    float s = bias;
                    #pragma unroll
                    for (int f = 0; f < Fsz; ++f)
                        s += xin[(r0 + i) * 16 + f] * w1r[f];
                    z[i] += s;
                }
            } else {
                #pragma unroll
                for (int i = 0; i < 6; ++i) z[i] += xzv[i];
            }
        }
        #pragma unroll
        for (int i = 0; i < 6; ++i) zsw[i] = z[i];
        __syncthreads();

        // ---- gate combine: 384 cells, 1 per thread ----
        if (tid < RPT * 16) {
            int j = tid & 15, r = tid >> 4;
            int row = rbase + r;
            if (row < Bsz) {
                float zi = zs0[( 0 + j) * ZS_LD + r] + zs1[( 0 + j) * ZS_LD + r];
                float zf = zs0[(16 + j) * ZS_LD + r] + zs1[(16 + j) * ZS_LD + r];
                float zg = zs0[(32 + j) * ZS_LD + r] + zs1[(32 + j) * ZS_LD + r];
                float zo = zs0[(48 + j) * ZS_LD + r] + zs1[(48 + j) * ZS_LD + r];
                float ig = sigmoidf_(zi), fg = sigmoidf_(zf);
                float gv = tanh_acc(zg),  og = sigmoidf_(zo);
                float cn = fg * csh[tid] + ig * gv;
                csh[tid] = cn;
                float hn = og * tanh_acc(cn);
                int gidx = row * Hsz + jbase + j;
                hout[gidx] = hn;
                if (layer == 0) g_seq[(size_t)t * Bsz * Hsz + gidx] = hn;
            }
        }

        // ---- release ----
        __syncthreads();
        if (tid == 0) {
            __threadfence();
            unsigned n = atomicAdd(&g_cnt[layer][grp], 1u);
            if (n == NCOLT - 1) {
                g_cnt[layer][grp] = 0u;
                __threadfence();
                atomicExch(&g_flag[layer][grp], (unsigned)(t + 1));
            }
        }
    }
}

// proj2: xz2 = seq @ W2 + b2  ([50000,256]x[256,1024])
__global__ __launch_bounds__(256, 1) void proj2(const float* __restrict__ W2,
                                                const float* __restrict__ b2) {
    extern __shared__ float sm[];
    float* ws = sm;                 // [64][256] swizzled W strip
    float* At = sm + 64 * 256;      // [128][256] row-major A tile
    const int tid = threadIdx.x;
    const int nbase = blockIdx.x * 64;
    const int mbase = blockIdx.y * P2M;
    const int M = Tsz * Bsz;

    #pragma unroll
    for (int bb = 0; bb < 8; ++bb) {
        float tf[8];
        #pragma unroll
        for (int i = 0; i < 8; ++i) {
            int idx = tid + (bb * 8 + i) * 256;
            int k = idx >> 6, c = idx & 63;
            tf[i] = __ldg(W2 + k * G4 + nbase + c);
        }
        #pragma unroll
        for (int i = 0; i < 8; ++i) {
            int idx = tid + (bb * 8 + i) * 256;
            int k = idx >> 6, c = idx & 63;
            ws[c * 256 + (k ^ ((c & 7) << 2))] = tf[i];
        }
    }
    {
        const float4* sq4 = (const float4*)g_seq;
        float4* At4 = (float4*)At;
        #pragma unroll
        for (int bb = 0; bb < 4; ++bb) {
            float4 tf[8];
            #pragma unroll
            for (int i = 0; i < 8; ++i) {
                int idx = tid + (bb * 8 + i) * 256;
                int r = idx >> 6, k4 = idx & 63;
                int m = mbase + r;
                tf[i] = (m < M) ? __ldg(sq4 + (size_t)m * 64 + k4)
                                : make_float4(0.f, 0.f, 0.f, 0.f);
            }
            #pragma unroll
            for (int i = 0; i < 8; ++i)
                At4[tid + (bb * 8 + i) * 256] = tf[i];
        }
    }
    __syncthreads();

    const int tx = tid & 63;
    const int ty = tid >> 6;
    const int r0 = ty * 32;
    const int xs = (tx & 7) << 2;
    const float* wsl = ws + tx * 256;
    const float* al  = At + r0 * 256;

    unsigned long long acc[32];
    #pragma unroll
    for (int i = 0; i < 32; ++i) acc[i] = 0ull;

    #pragma unroll 1
    for (int k = 0; k < 256; k += 4) {
        ulonglong2 uv = *reinterpret_cast<const ulonglong2*>(wsl + (k ^ xs));
        #pragma unroll
        for (int i = 0; i < 32; ++i) {
            ulonglong2 hv = *reinterpret_cast<const ulonglong2*>(al + i * 256 + k);
            ffma2(acc[i], hv.x, uv.x);
            ffma2(acc[i], hv.y, uv.y);
        }
    }
    float bb2 = b2[nbase + tx];
    #pragma unroll
    for (int i = 0; i < 32; ++i) {
        int m = mbase + r0 + i;
        if (m < M) {
            float lo, hi;
            unpack2(acc[i], lo, hi);
            g_xz2[(size_t)m * G4 + nbase + tx] = lo + hi + bb2;
        }
    }
}

__global__ __launch_bounds__(256) void head(const float* __restrict__ Wd,
                                            const float* __restrict__ bd,
                                            const float* __restrict__ Ws,
                                            const float* __restrict__ bs,
                                            float* __restrict__ out) {
    __shared__ float hrow[Hsz];
    __shared__ float hid[Dsz];
    __shared__ float lbuf[Csz];
    __shared__ float ebuf[Csz];
    int b = blockIdx.x, tid = threadIdx.x;
    hrow[tid] = g_h2a[b * Hsz + tid];   // t=249 odd -> buffer 'a'
    __syncthreads();
    if (tid < Dsz) {
        float s = bd[tid];
        #pragma unroll 8
        for (int k = 0; k < Hsz; ++k) s += hrow[k] * Wd[k * Dsz + tid];
        hid[tid] = fmaxf(s, 0.f);
    }
    __syncthreads();
    if (tid < Csz) {
        float s = bs[tid];
        for (int d = 0; d < Dsz; ++d) s += hid[d] * Ws[d * Csz + tid];
        lbuf[tid] = s;
    }
    __syncthreads();
    if (tid < Csz) {
        float m = lbuf[0];
        #pragma unroll
        for (int j = 1; j < Csz; ++j) m = fmaxf(m, lbuf[j]);
        ebuf[tid] = __expf(lbuf[tid] - m);
    }
    __syncthreads();
    if (tid < Csz) {
        float sum = 0.f;
        #pragma unroll
        for (int j = 0; j < Csz; ++j) sum += ebuf[j];
        out[b * Csz + tid] = ebuf[tid] / sum;
    }
}

extern "C" void kernel_launch(void* const* d_in, const int* in_sizes, int n_in,
                              void* d_out, int out_size) {
    (void)in_sizes; (void)n_in; (void)out_size;
    const float* inputs = (const float*)d_in[0];
    const float* W1 = (const float*)d_in[1];
    const float* U1 = (const float*)d_in[2];
    const float* b1 = (const float*)d_in[3];
    const float* W2 = (const float*)d_in[4];
    const float* U2 = (const float*)d_in[5];
    const float* b2 = (const float*)d_in[6];
    const float* Wd = (const float*)d_in[7];
    const float* bd = (const float*)d_in[8];
    const float* Ws = (const float*)d_in[9];
    const float* bs = (const float*)d_in[10];
    float* out = (float*)d_out;

    // pad lstm smem to 120KB so only 1 CTA/SM fits (guarantees 144-CTA co-residency)
    const int SM_STEP = 120 * 1024;
    const int SM_PROJ = (64 * 256 + P2M * 256) * 4;   // 192KB
    cudaFuncSetAttribute(lstm_layer, cudaFuncAttributeMaxDynamicSharedMemorySize, SM_STEP);
    cudaFuncSetAttribute(proj2,      cudaFuncAttributeMaxDynamicSharedMemorySize, SM_PROJ);

    zero_state<<<1, 32>>>();

    dim3 lg(NCOLT, NROWT);
    lstm_layer<<<lg, 512, SM_STEP>>>(0, U1, W1, b1, inputs);
    proj2<<<dim3(16, (Tsz * Bsz + P2M - 1) / P2M), 256, SM_PROJ>>>(W2, b2);
    lstm_layer<<<lg, 512, SM_STEP>>>(1, U2, W1, b1, inputs);
    head<<<Bsz, 256>>>(Wd, bd, Ws, bs, out);
}

// round 12
// speedup vs baseline: 2.3215x; 1.2070x over previous
#include <cuda_runtime.h>

#define Bsz 200
#define Tsz 250
#define Fsz 14
#define Hsz 256
#define G4  1024
#define Dsz 164
#define Csz 8
#define NCOLT 16
#define NROWT 9
#define RPT   24
#define ZS_LD 25
#define P2M   128

__device__ float g_xz2[Tsz * Bsz * G4];
__device__ float g_seq[Tsz * Bsz * Hsz];
__device__ float g_h1a[Bsz * Hsz];
__device__ float g_h1b[Bsz * Hsz];
__device__ float g_h2a[Bsz * Hsz];
__device__ float g_h2b[Bsz * Hsz];
__device__ unsigned g_scnt[2][NROWT][Tsz];   // per-step arrival counters

__device__ __forceinline__ void ffma2(unsigned long long& d, unsigned long long a, unsigned long long b) {
    asm("fma.rn.f32x2 %0, %1, %2, %0;" : "+l"(d) : "l"(a), "l"(b));
}
__device__ __forceinline__ void unpack2(unsigned long long v, float& lo, float& hi) {
    unsigned int l, h;
    asm("mov.b64 {%0, %1}, %2;" : "=r"(l), "=r"(h) : "l"(v));
    lo = __uint_as_float(l); hi = __uint_as_float(h);
}
// ACCURATE activations — the recurrence compounds error over 250 steps.
// Fast __expf tanh measured at rel_err 1.2e-3 (FAIL); these give 6.9e-8.
__device__ __forceinline__ float sigmoidf_(float x) {
    return 1.0f / (1.0f + __expf(-x));
}
__device__ __forceinline__ float tanh_acc(float x) { return tanhf(x); }

__global__ void zero_state() {
    int i = blockIdx.x * blockDim.x + threadIdx.x;
    if (i < 2 * NROWT * Tsz) ((unsigned*)g_scnt)[i] = 0u;
}

// persistent LSTM layer: grid (16,9)=144 CTAs, 512 thr, all 250 steps inside.
// CTA tile 24 rows x 16 h-cols (64 gate cols).
// thread = 2 gate-cols (c, c+32) x 6 rows x k-quarter:
//   c = tid&31, rowthr = (tid>>5)&3 (r0 = rowthr*6), kg = tid>>7 (k in [kg*64, kg*64+64))
__global__ __launch_bounds__(512, 1) void lstm_layer(
    int layer, const float* __restrict__ U,
    const float* __restrict__ W1, const float* __restrict__ b1,
    const float* __restrict__ inputs)
{
    extern __shared__ float smem[];
    float* ust = smem;                    // [64][256] U strip, k-swizzled per col
    float* hst = ust + 64 * 256;          // [24][256] h tile, row-major
    float* zs  = hst + RPT * 256;         // [4][64][ZS_LD] partials per k-quarter
    float* w1s = zs + 4 * 64 * ZS_LD;     // [14][64]
    float* b1s = w1s + Fsz * 64;          // [64]
    float* xin = b1s + 64;                // [24][16]
    __shared__ float csh[RPT * 16];       // cell state, CTA-private

    const int tid   = threadIdx.x;
    const int jbase = blockIdx.x * 16;
    const int grp   = blockIdx.y;
    const int rbase = grp * RPT;

    float* ha = layer ? g_h2a : g_h1a;
    float* hb = layer ? g_h2b : g_h1b;

    // ---- one-time staging: U strip (16384 floats, 32/thread, batched) ----
    #pragma unroll
    for (int bb = 0; bb < 4; ++bb) {
        float tf[8];
        #pragma unroll
        for (int i = 0; i < 8; ++i) {
            int idx = tid + (bb * 8 + i) * 512;
            int k = idx >> 6, c = idx & 63;
            tf[i] = __ldg(U + k * G4 + ((c >> 4) << 8) + jbase + (c & 15));
        }
        #pragma unroll
        for (int i = 0; i < 8; ++i) {
            int idx = tid + (bb * 8 + i) * 512;
            int k = idx >> 6, c = idx & 63;
            ust[c * 256 + (k ^ ((c & 7) << 2))] = tf[i];
        }
    }
    if (layer == 0) {
        for (int idx = tid; idx < Fsz * 64; idx += 512) {
            int f = idx >> 6, c = idx & 63;
            w1s[idx] = W1[f * G4 + ((c >> 4) << 8) + jbase + (c & 15)];
        }
        if (tid < 64) b1s[tid] = b1[((tid >> 4) << 8) + jbase + (tid & 15)];
    }
    if (tid < RPT * 16) csh[tid] = 0.f;

    const int c      = tid & 31;          // col-thread: owns cols c and c+32
    const int rowthr = (tid >> 5) & 3;
    const int kg     = tid >> 7;
    const int r0     = rowthr * 6;
    const int kbase  = kg * 64;
    const int xs     = (c & 7) << 2;      // same swizzle for c and c+32
    const float* u0 = ust + c * 256 + kbase;
    const float* u1 = ust + (c + 32) * 256 + kbase;
    const float* hlp = hst + r0 * 256 + kbase;
    float* zq = zs + kg * (64 * ZS_LD);
    const int colA = ((c >> 4) << 8) + jbase + (c & 15);
    const int colB = (((c + 32) >> 4) << 8) + jbase + ((c + 32) & 15);

    // layer-0 xin prefetch mapping (one cell per thread, tid<384)
    const int xr = tid >> 4, xf = tid & 15;

    for (int t = 0; t < Tsz; ++t) {
        const float* hin  = (t & 1) ? hb : ha;
        float*       hout = (t & 1) ? ha : hb;

        // ---- prefetch (regs, independent of h(t)) ----
        float xp = 0.f;
        float xzvA[6], xzvB[6];
        if (layer == 0) {
            if (tid < RPT * 16) {
                int row = rbase + xr;
                if (row < Bsz && xf < Fsz)
                    xp = __ldg(inputs + ((size_t)row * Tsz + t) * Fsz + xf);
            }
        } else if (kg == 0) {
            const float* xzt = g_xz2 + (size_t)t * Bsz * G4;
            #pragma unroll
            for (int i = 0; i < 6; ++i) {
                int row = rbase + r0 + i;
                xzvA[i] = (row < Bsz) ? __ldg(xzt + (size_t)row * G4 + colA) : 0.f;
                xzvB[i] = (row < Bsz) ? __ldg(xzt + (size_t)row * G4 + colB) : 0.f;
            }
        }

        // ---- wait for step t-1 completion of this row group ----
        if (t > 0) {
            if (tid == 0) {
                volatile unsigned* sc = &g_scnt[layer][grp][t - 1];
                while (*sc != (unsigned)NCOLT) { }
                __threadfence();
            }
        }
        __syncthreads();

        // ---- stage h tile (1536 float4, 3/thread, batched) ----
        if (t == 0) {
            #pragma unroll
            for (int i = 0; i < 3; ++i)
                ((float4*)hst)[tid + i * 512] = make_float4(0.f, 0.f, 0.f, 0.f);
        } else {
            const float4* hin4 = (const float4*)hin;
            float4 tf[3];
            #pragma unroll
            for (int i = 0; i < 3; ++i) {
                int idx = tid + i * 512;
                int r = idx >> 6, k4 = idx & 63;
                int row = rbase + r;
                tf[i] = (row < Bsz) ? __ldcg(hin4 + (size_t)row * 64 + k4)
                                    : make_float4(0.f, 0.f, 0.f, 0.f);
            }
            #pragma unroll
            for (int i = 0; i < 3; ++i)
                ((float4*)hst)[tid + i * 512] = tf[i];
        }
        if (layer == 0 && tid < RPT * 16) xin[tid] = xp;
        __syncthreads();

        // ---- recurrent GEMM (2 cols x 6 rows, this k-quarter) ----
        unsigned long long A0[6], A1[6];
        #pragma unroll
        for (int i = 0; i < 6; ++i) { A0[i] = 0ull; A1[i] = 0ull; }
        #pragma unroll 4
        for (int k = 0; k < 64; k += 4) {
            ulonglong2 uva = *reinterpret_cast<const ulonglong2*>(u0 + (k ^ xs));
            ulonglong2 uvb = *reinterpret_cast<const ulonglong2*>(u1 + (k ^ xs));
            #pragma unroll
            for (int i = 0; i < 6; ++i) {
                ulonglong2 hv = *reinterpret_cast<const ulonglong2*>(hlp + i * 256 + k);
                ffma2(A0[i], hv.x, uva.x); ffma2(A0[i], hv.y, uva.y);
                ffma2(A1[i], hv.x, uvb.x); ffma2(A1[i], hv.y, uvb.y);
            }
        }
        float zA[6], zB[6];
        #pragma unroll
        for (int i = 0; i < 6; ++i) {
            float lo, hi;
            unpack2(A0[i], lo, hi); zA[i] = lo + hi;
            unpack2(A1[i], lo, hi); zB[i] = lo + hi;
        }

        // kg=0 folds in the input-path contribution for both cols
        if (kg == 0) {
            if (layer == 0) {
                float wA[Fsz], wB[Fsz];
                #pragma unroll
                for (int f = 0; f < Fsz; ++f) {
                    wA[f] = w1s[f * 64 + c];
                    wB[f] = w1s[f * 64 + c + 32];
                }
                float bA = b1s[c], bB = b1s[c + 32];
                #pragma unroll
                for (int i = 0; i < 6; ++i) {
                    float sA = bA, sB = bB;
                    #pragma unroll
                    for (int f = 0; f < Fsz; ++f) {
                        float xv = xin[(r0 + i) * 16 + f];
                        sA += xv * wA[f];
                        sB += xv * wB[f];
                    }
                    zA[i] += sA;
                    zB[i] += sB;
                }
            } else {
                #pragma unroll
                for (int i = 0; i < 6; ++i) { zA[i] += xzvA[i]; zB[i] += xzvB[i]; }
            }
        }
        #pragma unroll
        for (int i = 0; i < 6; ++i) {
            zq[c * ZS_LD + r0 + i]        = zA[i];
            zq[(c + 32) * ZS_LD + r0 + i] = zB[i];
        }
        __syncthreads();

        // ---- gate combine: 384 cells, 1 per thread; sum 4 k-quarter partials ----
        if (tid < RPT * 16) {
            int j = tid & 15, r = tid >> 4;
            int row = rbase + r;
            if (row < Bsz) {
                float zg4[4];
                #pragma unroll
                for (int g = 0; g < 4; ++g) {
                    float s = 0.f;
                    #pragma unroll
                    for (int q = 0; q < 4; ++q)
                        s += zs[q * (64 * ZS_LD) + (g * 16 + j) * ZS_LD + r];
                    zg4[g] = s;
                }
                float ig = sigmoidf_(zg4[0]), fg = sigmoidf_(zg4[1]);
                float gv = tanh_acc(zg4[2]), og = sigmoidf_(zg4[3]);
                float cn = fg * csh[tid] + ig * gv;
                csh[tid] = cn;
                float hn = og * tanh_acc(cn);
                int gidx = row * Hsz + jbase + j;
                hout[gidx] = hn;
                if (layer == 0) g_seq[(size_t)t * Bsz * Hsz + gidx] = hn;
            }
        }

        // ---- release: fire-and-forget arrival into this step's counter ----
        __syncthreads();
        if (tid == 0) {
            __threadfence();
            atomicAdd(&g_scnt[layer][grp][t], 1u);   // result unused -> RED
        }
    }
}

// proj2: xz2 = seq @ W2 + b2  ([50000,256]x[256,1024])
__global__ __launch_bounds__(256, 1) void proj2(const float* __restrict__ W2,
                                                const float* __restrict__ b2) {
    extern __shared__ float sm[];
    float* ws = sm;                 // [64][256] swizzled W strip
    float* At = sm + 64 * 256;      // [128][256] row-major A tile
    const int tid = threadIdx.x;
    const int nbase = blockIdx.x * 64;
    const int mbase = blockIdx.y * P2M;
    const int M = Tsz * Bsz;

    #pragma unroll
    for (int bb = 0; bb < 8; ++bb) {
        float tf[8];
        #pragma unroll
        for (int i = 0; i < 8; ++i) {
            int idx = tid + (bb * 8 + i) * 256;
            int k = idx >> 6, c = idx & 63;
            tf[i] = __ldg(W2 + k * G4 + nbase + c);
        }
        #pragma unroll
        for (int i = 0; i < 8; ++i) {
            int idx = tid + (bb * 8 + i) * 256;
            int k = idx >> 6, c = idx & 63;
            ws[c * 256 + (k ^ ((c & 7) << 2))] = tf[i];
        }
    }
    {
        const float4* sq4 = (const float4*)g_seq;
        float4* At4 = (float4*)At;
        #pragma unroll
        for (int bb = 0; bb < 4; ++bb) {
            float4 tf[8];
            #pragma unroll
            for (int i = 0; i < 8; ++i) {
                int idx = tid + (bb * 8 + i) * 256;
                int r = idx >> 6, k4 = idx & 63;
                int m = mbase + r;
                tf[i] = (m < M) ? __ldg(sq4 + (size_t)m * 64 + k4)
                                : make_float4(0.f, 0.f, 0.f, 0.f);
            }
            #pragma unroll
            for (int i = 0; i < 8; ++i)
                At4[tid + (bb * 8 + i) * 256] = tf[i];
        }
    }
    __syncthreads();

    const int tx = tid & 63;
    const int ty = tid >> 6;
    const int r0 = ty * 32;
    const int xs = (tx & 7) << 2;
    const float* wsl = ws + tx * 256;
    const float* al  = At + r0 * 256;

    unsigned long long acc[32];
    #pragma unroll
    for (int i = 0; i < 32; ++i) acc[i] = 0ull;

    #pragma unroll 1
    for (int k = 0; k < 256; k += 4) {
        ulonglong2 uv = *reinterpret_cast<const ulonglong2*>(wsl + (k ^ xs));
        #pragma unroll
        for (int i = 0; i < 32; ++i) {
            ulonglong2 hv = *reinterpret_cast<const ulonglong2*>(al + i * 256 + k);
            ffma2(acc[i], hv.x, uv.x);
            ffma2(acc[i], hv.y, uv.y);
        }
    }
    float bb2 = b2[nbase + tx];
    #pragma unroll
    for (int i = 0; i < 32; ++i) {
        int m = mbase + r0 + i;
        if (m < M) {
            float lo, hi;
            unpack2(acc[i], lo, hi);
            g_xz2[(size_t)m * G4 + nbase + tx] = lo + hi + bb2;
        }
    }
}

__global__ __launch_bounds__(256) void head(const float* __restrict__ Wd,
                                            const float* __restrict__ bd,
                                            const float* __restrict__ Ws,
                                            const float* __restrict__ bs,
                                            float* __restrict__ out) {
    __shared__ float hrow[Hsz];
    __shared__ float hid[Dsz];
    __shared__ float lbuf[Csz];
    __shared__ float ebuf[Csz];
    int b = blockIdx.x, tid = threadIdx.x;
    hrow[tid] = g_h2a[b * Hsz + tid];   // t=249 odd -> buffer 'a'
    __syncthreads();
    if (tid < Dsz) {
        float s = bd[tid];
        #pragma unroll 8
        for (int k = 0; k < Hsz; ++k) s += hrow[k] * Wd[k * Dsz + tid];
        hid[tid] = fmaxf(s, 0.f);
    }
    __syncthreads();
    if (tid < Csz) {
        float s = bs[tid];
        for (int d = 0; d < Dsz; ++d) s += hid[d] * Ws[d * Csz + tid];
        lbuf[tid] = s;
    }
    __syncthreads();
    if (tid < Csz) {
        float m = lbuf[0];
        #pragma unroll
        for (int j = 1; j < Csz; ++j) m = fmaxf(m, lbuf[j]);
        ebuf[tid] = __expf(lbuf[tid] - m);
    }
    __syncthreads();
    if (tid < Csz) {
        float sum = 0.f;
        #pragma unroll
        for (int j = 0; j < Csz; ++j) sum += ebuf[j];
        out[b * Csz + tid] = ebuf[tid] / sum;
    }
}

extern "C" void kernel_launch(void* const* d_in, const int* in_sizes, int n_in,
                              void* d_out, int out_size) {
    (void)in_sizes; (void)n_in; (void)out_size;
    const float* inputs = (const float*)d_in[0];
    const float* W1 = (const float*)d_in[1];
    const float* U1 = (const float*)d_in[2];
    const float* b1 = (const float*)d_in[3];
    const float* W2 = (const float*)d_in[4];
    const float* U2 = (const float*)d_in[5];
    const float* b2 = (const float*)d_in[6];
    const float* Wd = (const float*)d_in[7];
    const float* bd = (const float*)d_in[8];
    const float* Ws = (const float*)d_in[9];
    const float* bs = (const float*)d_in[10];
    float* out = (float*)d_out;

    // pad lstm smem so only 1 CTA/SM fits (guarantees 144-CTA co-residency)
    const int SM_STEP = 124 * 1024;
    const int SM_PROJ = (64 * 256 + P2M * 256) * 4;   // 192KB
    cudaFuncSetAttribute(lstm_layer, cudaFuncAttributeMaxDynamicSharedMemorySize, SM_STEP);
    cudaFuncSetAttribute(proj2,      cudaFuncAttributeMaxDynamicSharedMemorySize, SM_PROJ);

    zero_state<<<(2 * NROWT * Tsz + 255) / 256, 256>>>();

    dim3 lg(NCOLT, NROWT);
    lstm_layer<<<lg, 512, SM_STEP>>>(0, U1, W1, b1, inputs);
    proj2<<<dim3(16, (Tsz * Bsz + P2M - 1) / P2M), 256, SM_PROJ>>>(W2, b2);
    lstm_layer<<<lg, 512, SM_STEP>>>(1, U2, W1, b1, inputs);
    head<<<Bsz, 256>>>(Wd, bd, Ws, bs, out);
}

// round 13
// speedup vs baseline: 2.5471x; 1.0971x over previous
#include <cuda_runtime.h>

#define Bsz 200
#define Tsz 250
#define Fsz 14
#define Hsz 256
#define G4  1024
#define Dsz 164
#define Csz 8
#define NCOLT 16
#define NROWT 9
#define RPT   24
#define ZS_LD 25
#define P2M   128

__device__ float g_xz2[Tsz * Bsz * G4];
__device__ float g_seq[Tsz * Bsz * Hsz];
__device__ float g_h1a[Bsz * Hsz];
__device__ float g_h1b[Bsz * Hsz];
__device__ float g_h2a[Bsz * Hsz];
__device__ float g_h2b[Bsz * Hsz];
__device__ unsigned g_scnt[2][NROWT][Tsz];   // per-step arrival counters

__device__ __forceinline__ void ffma2(unsigned long long& d, unsigned long long a, unsigned long long b) {
    asm("fma.rn.f32x2 %0, %1, %2, %0;" : "+l"(d) : "l"(a), "l"(b));
}
__device__ __forceinline__ void unpack2(unsigned long long v, float& lo, float& hi) {
    unsigned int l, h;
    asm("mov.b64 {%0, %1}, %2;" : "=r"(l), "=r"(h) : "l"(v));
    lo = __uint_as_float(l); hi = __uint_as_float(h);
}
__device__ __forceinline__ unsigned ld_acquire(const unsigned* p) {
    unsigned v;
    asm volatile("ld.acquire.gpu.u32 %0, [%1];" : "=r"(v) : "l"(p) : "memory");
    return v;
}
// ACCURATE activations — the recurrence compounds error over 250 steps.
// Fast __expf tanh measured at rel_err 1.2e-3 (FAIL); these give 6.9e-8.
__device__ __forceinline__ float sigmoidf_(float x) {
    return 1.0f / (1.0f + __expf(-x));
}
__device__ __forceinline__ float tanh_acc(float x) { return tanhf(x); }

__global__ void zero_state() {
    int i = blockIdx.x * blockDim.x + threadIdx.x;
    if (i < 2 * NROWT * Tsz) ((unsigned*)g_scnt)[i] = 0u;
}

// persistent LSTM layer: grid (16,9)=144 CTAs, 512 thr, all 250 steps inside.
// CTA tile 24 rows x 16 h-cols (64 gate cols).
// thread = 2 gate-cols (c, c+32) x 6 rows x k-quarter.
// U strip uses ROTATION swizzle: ust[c][(k/4 + c) & 63] (16B units) ->
// 32 distinct cols per warp hit 32 distinct banks (was 4-way conflicted).
__global__ __launch_bounds__(512, 1) void lstm_layer(
    int layer, const float* __restrict__ U,
    const float* __restrict__ W1, const float* __restrict__ b1,
    const float* __restrict__ inputs)
{
    extern __shared__ float smem[];
    float* ust = smem;                    // [64][256] U strip, rotation-swizzled
    float* hst = ust + 64 * 256;          // [24][256] h tile, row-major
    float* zs  = hst + RPT * 256;         // [4][64][ZS_LD] partials per k-quarter
    float* w1s = zs + 4 * 64 * ZS_LD;     // [14][64]
    float* b1s = w1s + Fsz * 64;          // [64]
    float* xin = b1s + 64;                // [24][16]
    __shared__ float csh[RPT * 16];       // cell state, CTA-private

    const int tid   = threadIdx.x;
    const int jbase = blockIdx.x * 16;
    const int grp   = blockIdx.y;
    const int rbase = grp * RPT;

    float* ha = layer ? g_h2a : g_h1a;
    float* hb = layer ? g_h2b : g_h1b;

    // ---- one-time staging: U strip (rotation swizzle) ----
    #pragma unroll
    for (int bb = 0; bb < 4; ++bb) {
        float tf[8];
        #pragma unroll
        for (int i = 0; i < 8; ++i) {
            int idx = tid + (bb * 8 + i) * 512;
            int k = idx >> 6, c = idx & 63;
            tf[i] = __ldg(U + k * G4 + ((c >> 4) << 8) + jbase + (c & 15));
        }
        #pragma unroll
        for (int i = 0; i < 8; ++i) {
            int idx = tid + (bb * 8 + i) * 512;
            int k = idx >> 6, c = idx & 63;
            ust[c * 256 + ((((k >> 2) + c) & 63) << 2) + (k & 3)] = tf[i];
        }
    }
    if (layer == 0) {
        for (int idx = tid; idx < Fsz * 64; idx += 512) {
            int f = idx >> 6, c = idx & 63;
            w1s[idx] = W1[f * G4 + ((c >> 4) << 8) + jbase + (c & 15)];
        }
        if (tid < 64) b1s[tid] = b1[((tid >> 4) << 8) + jbase + (tid & 15)];
    }
    if (tid < RPT * 16) csh[tid] = 0.f;

    const int c      = tid & 31;          // col-thread: owns cols c and c+32
    const int rowthr = (tid >> 5) & 3;
    const int kg     = tid >> 7;
    const int r0     = rowthr * 6;
    const int kbase  = kg * 64;
    const float* u0 = ust + c * 256;
    const float* u1 = ust + (c + 32) * 256;
    const int o0 = (kbase >> 2) + c;          // rotation bases (mod 64 at use)
    const int o1 = (kbase >> 2) + c + 32;
    const float* hlp = hst + r0 * 256 + kbase;
    float* zq = zs + kg * (64 * ZS_LD);
    const int colA = ((c >> 4) << 8) + jbase + (c & 15);
    const int colB = (((c + 32) >> 4) << 8) + jbase + ((c + 32) & 15);

    // layer-0 xin prefetch mapping (one cell per thread, tid<384)
    const int xr = tid >> 4, xf = tid & 15;

    for (int t = 0; t < Tsz; ++t) {
        const float* hin  = (t & 1) ? hb : ha;
        float*       hout = (t & 1) ? ha : hb;

        // ---- prefetch (regs, independent of h(t)) ----
        float xp = 0.f;
        float xzvA[6], xzvB[6];
        if (layer == 0) {
            if (tid < RPT * 16) {
                int row = rbase + xr;
                if (row < Bsz && xf < Fsz)
                    xp = __ldg(inputs + ((size_t)row * Tsz + t) * Fsz + xf);
            }
        } else if (kg == 0) {
            const float* xzt = g_xz2 + (size_t)t * Bsz * G4;
            #pragma unroll
            for (int i = 0; i < 6; ++i) {
                int row = rbase + r0 + i;
                xzvA[i] = (row < Bsz) ? __ldg(xzt + (size_t)row * G4 + colA) : 0.f;
                xzvB[i] = (row < Bsz) ? __ldg(xzt + (size_t)row * G4 + colB) : 0.f;
            }
        }

        // ---- warp-autonomous wait for step t-1 of this row group ----
        if (t > 0) {
            if ((tid & 31) == 0) {
                const unsigned* sc = &g_scnt[layer][grp][t - 1];
                while (ld_acquire(sc) != (unsigned)NCOLT) { }
            }
            __syncwarp();
        }

        // ---- stage h tile (each warp its chunk, right after its own poll) ----
        if (t == 0) {
            #pragma unroll
            for (int i = 0; i < 3; ++i)
                ((float4*)hst)[tid + i * 512] = make_float4(0.f, 0.f, 0.f, 0.f);
        } else {
            const float4* hin4 = (const float4*)hin;
            float4 tf[3];
            #pragma unroll
            for (int i = 0; i < 3; ++i) {
                int idx = tid + i * 512;
                int r = idx >> 6, k4 = idx & 63;
                int row = rbase + r;
                tf[i] = (row < Bsz) ? __ldcg(hin4 + (size_t)row * 64 + k4)
                                    : make_float4(0.f, 0.f, 0.f, 0.f);
            }
            #pragma unroll
            for (int i = 0; i < 3; ++i)
                ((float4*)hst)[tid + i * 512] = tf[i];
        }
        if (layer == 0 && tid < RPT * 16) xin[tid] = xp;
        __syncthreads();

        // ---- recurrent GEMM (2 cols x 6 rows, this k-quarter) ----
        unsigned long long A0[6], A1[6];
        #pragma unroll
        for (int i = 0; i < 6; ++i) { A0[i] = 0ull; A1[i] = 0ull; }
        #pragma unroll 4
        for (int k = 0; k < 64; k += 4) {
            int i4 = k >> 2;
            ulonglong2 uva = *reinterpret_cast<const ulonglong2*>(u0 + (((o0 + i4) & 63) << 2));
            ulonglong2 uvb = *reinterpret_cast<const ulonglong2*>(u1 + (((o1 + i4) & 63) << 2));
            #pragma unroll
            for (int i = 0; i < 6; ++i) {
                ulonglong2 hv = *reinterpret_cast<const ulonglong2*>(hlp + i * 256 + k);
                ffma2(A0[i], hv.x, uva.x); ffma2(A0[i], hv.y, uva.y);
                ffma2(A1[i], hv.x, uvb.x); ffma2(A1[i], hv.y, uvb.y);
            }
        }
        float zA[6], zB[6];
        #pragma unroll
        for (int i = 0; i < 6; ++i) {
            float lo, hi;
            unpack2(A0[i], lo, hi); zA[i] = lo + hi;
            unpack2(A1[i], lo, hi); zB[i] = lo + hi;
        }

        // kg=0 folds in the input-path contribution for both cols
        if (kg == 0) {
            if (layer == 0) {
                float wA[Fsz], wB[Fsz];
                #pragma unroll
                for (int f = 0; f < Fsz; ++f) {
                    wA[f] = w1s[f * 64 + c];
                    wB[f] = w1s[f * 64 + c + 32];
                }
                float bA = b1s[c], bB = b1s[c + 32];
                #pragma unroll
                for (int i = 0; i < 6; ++i) {
                    float sA = bA, sB = bB;
                    #pragma unroll
                    for (int f = 0; f < Fsz; ++f) {
                        float xv = xin[(r0 + i) * 16 + f];
                        sA += xv * wA[f];
                        sB += xv * wB[f];
                    }
                    zA[i] += sA;
                    zB[i] += sB;
                }
            } else {
                #pragma unroll
                for (int i = 0; i < 6; ++i) { zA[i] += xzvA[i]; zB[i] += xzvB[i]; }
            }
        }
        #pragma unroll
        for (int i = 0; i < 6; ++i) {
            zq[c * ZS_LD + r0 + i]        = zA[i];
            zq[(c + 32) * ZS_LD + r0 + i] = zB[i];
        }
        __syncthreads();

        // ---- gate combine: 384 cells, 1 per thread; sum 4 k-quarter partials ----
        float hn_keep = 0.f;
        int   gidx_keep = -1;
        if (tid < RPT * 16) {
            int j = tid & 15, r = tid >> 4;
            int row = rbase + r;
            if (row < Bsz) {
                float zg4[4];
                #pragma unroll
                for (int g = 0; g < 4; ++g) {
                    float s = 0.f;
                    #pragma unroll
                    for (int q = 0; q < 4; ++q)
                        s += zs[q * (64 * ZS_LD) + (g * 16 + j) * ZS_LD + r];
                    zg4[g] = s;
                }
                float ig = sigmoidf_(zg4[0]), fg = sigmoidf_(zg4[1]);
                float gv = tanh_acc(zg4[2]), og = sigmoidf_(zg4[3]);
                float cn = fg * csh[tid] + ig * gv;
                csh[tid] = cn;
                float hn = og * tanh_acc(cn);
                int gidx = row * Hsz + jbase + j;
                hout[gidx] = hn;                    // critical store first
                hn_keep = hn; gidx_keep = gidx;
            }
        }

        // ---- release: fire-and-forget arrival; g_seq store off critical path ----
        __syncthreads();
        if (tid == 0) {
            __threadfence();
            atomicAdd(&g_scnt[layer][grp][t], 1u);   // result unused -> RED
        }
        if (layer == 0 && gidx_keep >= 0)
            g_seq[(size_t)t * Bsz * Hsz + gidx_keep] = hn_keep;
    }
}

// proj2: xz2 = seq @ W2 + b2  ([50000,256]x[256,1024])
__global__ __launch_bounds__(256, 1) void proj2(const float* __restrict__ W2,
                                                const float* __restrict__ b2) {
    extern __shared__ float sm[];
    float* ws = sm;                 // [64][256] rotation-swizzled W strip
    float* At = sm + 64 * 256;      // [128][256] row-major A tile
    const int tid = threadIdx.x;
    const int nbase = blockIdx.x * 64;
    const int mbase = blockIdx.y * P2M;
    const int M = Tsz * Bsz;

    #pragma unroll
    for (int bb = 0; bb < 8; ++bb) {
        float tf[8];
        #pragma unroll
        for (int i = 0; i < 8; ++i) {
            int idx = tid + (bb * 8 + i) * 256;
            int k = idx >> 6, c = idx & 63;
            tf[i] = __ldg(W2 + k * G4 + nbase + c);
        }
        #pragma unroll
        for (int i = 0; i < 8; ++i) {
            int idx = tid + (bb * 8 + i) * 256;
            int k = idx >> 6, c = idx & 63;
            ws[c * 256 + ((((k >> 2) + c) & 63) << 2) + (k & 3)] = tf[i];
        }
    }
    {
        const float4* sq4 = (const float4*)g_seq;
        float4* At4 = (float4*)At;
        #pragma unroll
        for (int bb = 0; bb < 4; ++bb) {
            float4 tf[8];
            #pragma unroll
            for (int i = 0; i < 8; ++i) {
                int idx = tid + (bb * 8 + i) * 256;
                int r = idx >> 6, k4 = idx & 63;
                int m = mbase + r;
                tf[i] = (m < M) ? __ldg(sq4 + (size_t)m * 64 + k4)
                                : make_float4(0.f, 0.f, 0.f, 0.f);
            }
            #pragma unroll
            for (int i = 0; i < 8; ++i)
                At4[tid + (bb * 8 + i) * 256] = tf[i];
        }
    }
    __syncthreads();

    const int tx = tid & 63;
    const int ty = tid >> 6;
    const int r0 = ty * 32;
    const float* wsl = ws + tx * 256;
    const float* al  = At + r0 * 256;

    unsigned long long acc[32];
    #pragma unroll
    for (int i = 0; i < 32; ++i) acc[i] = 0ull;

    #pragma unroll 1
    for (int k = 0; k < 256; k += 4) {
        int i4 = k >> 2;
        ulonglong2 uv = *reinterpret_cast<const ulonglong2*>(wsl + (((tx + i4) & 63) << 2));
        #pragma unroll
        for (int i = 0; i < 32; ++i) {
            ulonglong2 hv = *reinterpret_cast<const ulonglong2*>(al + i * 256 + k);
            ffma2(acc[i], hv.x, uv.x);
            ffma2(acc[i], hv.y, uv.y);
        }
    }
    float bb2 = b2[nbase + tx];
    #pragma unroll
    for (int i = 0; i < 32; ++i) {
        int m = mbase + r0 + i;
        if (m < M) {
            float lo, hi;
            unpack2(acc[i], lo, hi);
            g_xz2[(size_t)m * G4 + nbase + tx] = lo + hi + bb2;
        }
    }
}

__global__ __launch_bounds__(256) void head(const float* __restrict__ Wd,
                                            const float* __restrict__ bd,
                                            const float* __restrict__ Ws,
                                            const float* __restrict__ bs,
                                            float* __restrict__ out) {
    __shared__ float hrow[Hsz];
    __shared__ float hid[Dsz];
    __shared__ float lbuf[Csz];
    __shared__ float ebuf[Csz];
    int b = blockIdx.x, tid = threadIdx.x;
    hrow[tid] = g_h2a[b * Hsz + tid];   // t=249 odd -> buffer 'a'
    __syncthreads();
    if (tid < Dsz) {
        float s = bd[tid];
        #pragma unroll 8
        for (int k = 0; k < Hsz; ++k) s += hrow[k] * Wd[k * Dsz + tid];
        hid[tid] = fmaxf(s, 0.f);
    }
    __syncthreads();
    if (tid < Csz) {
        float s = bs[tid];
        for (int d = 0; d < Dsz; ++d) s += hid[d] * Ws[d * Csz + tid];
        lbuf[tid] = s;
    }
    __syncthreads();
    if (tid < Csz) {
        float m = lbuf[0];
        #pragma unroll
        for (int j = 1; j < Csz; ++j) m = fmaxf(m, lbuf[j]);
        ebuf[tid] = __expf(lbuf[tid] - m);
    }
    __syncthreads();
    if (tid < Csz) {
        float sum = 0.f;
        #pragma unroll
        for (int j = 0; j < Csz; ++j) sum += ebuf[j];
        out[b * Csz + tid] = ebuf[tid] / sum;
    }
}

extern "C" void kernel_launch(void* const* d_in, const int* in_sizes, int n_in,
                              void* d_out, int out_size) {
    (void)in_sizes; (void)n_in; (void)out_size;
    const float* inputs = (const float*)d_in[0];
    const float* W1 = (const float*)d_in[1];
    const float* U1 = (const float*)d_in[2];
    const float* b1 = (const float*)d_in[3];
    const float* W2 = (const float*)d_in[4];
    const float* U2 = (const float*)d_in[5];
    const float* b2 = (const float*)d_in[6];
    const float* Wd = (const float*)d_in[7];
    const float* bd = (const float*)d_in[8];
    const float* Ws = (const float*)d_in[9];
    const float* bs = (const float*)d_in[10];
    float* out = (float*)d_out;

    // pad lstm smem so only 1 CTA/SM fits (guarantees 144-CTA co-residency)
    const int SM_STEP = 124 * 1024;
    const int SM_PROJ = (64 * 256 + P2M * 256) * 4;   // 192KB
    cudaFuncSetAttribute(lstm_layer, cudaFuncAttributeMaxDynamicSharedMemorySize, SM_STEP);
    cudaFuncSetAttribute(proj2,      cudaFuncAttributeMaxDynamicSharedMemorySize, SM_PROJ);

    zero_state<<<(2 * NROWT * Tsz + 255) / 256, 256>>>();

    dim3 lg(NCOLT, NROWT);
    lstm_layer<<<lg, 512, SM_STEP>>>(0, U1, W1, b1, inputs);
    proj2<<<dim3(16, (Tsz * Bsz + P2M - 1) / P2M), 256, SM_PROJ>>>(W2, b2);
    lstm_layer<<<lg, 512, SM_STEP>>>(1, U2, W1, b1, inputs);
    head<<<Bsz, 256>>>(Wd, bd, Ws, bs, out);
}